// round 8
// baseline (speedup 1.0000x reference)
#include <cuda_runtime.h>
#include <cstdint>

// AUGRU, B=2048, T=200, D=H=64.
//  K1 (pre): Y = x@[Wgx|Wcx] + bias, k-pair-packed FFMA2 (no splats),
//            W transposed in smem, 6x6 thread tile, depth-2 cp.async.
//  K2 (rec): R7 skeleton (proven 358us) + tree-structured reductions.

#define B_ 2048
#define T_ 200
#define D_ 64
#define H_ 64
#define BT_ (B_ * T_)

typedef unsigned long long ull;

__device__ float Y1g[BT_ * 128];
__device__ float Y2g[BT_ * 64];

__device__ __forceinline__ ull pack2(float lo, float hi) {
    ull r; asm("mov.b64 %0, {%1, %2};" : "=l"(r) : "f"(lo), "f"(hi)); return r;
}
__device__ __forceinline__ void unpack2(ull v, float& lo, float& hi) {
    asm("mov.b64 {%0, %1}, %2;" : "=f"(lo), "=f"(hi) : "l"(v));
}
__device__ __forceinline__ ull ffma2(ull a, ull b, ull c) {
    ull d; asm("fma.rn.f32x2 %0, %1, %2, %3;" : "=l"(d) : "l"(a), "l"(b), "l"(c)); return d;
}
__device__ __forceinline__ ull add2(ull a, ull b) {
    ull d; asm("add.rn.f32x2 %0, %1, %2;" : "=l"(d) : "l"(a), "l"(b)); return d;
}
__device__ __forceinline__ float hadd2(ull v) {
    float lo, hi; unpack2(v, lo, hi); return lo + hi;
}
__device__ __forceinline__ float sigmoid_f(float x) {
    return __fdividef(1.0f, 1.0f + __expf(-x));
}
__device__ __forceinline__ float tanh_f(float x) {
    float e = __expf(2.0f * x);
    return 1.0f - __fdividef(2.0f, e + 1.0f);
}
__device__ __forceinline__ void cpa16(void* s, const void* g) {
    uint32_t sa = (uint32_t)__cvta_generic_to_shared(s);
    asm volatile("cp.async.ca.shared.global [%0], [%1], 16;" :: "r"(sa), "l"(g));
}
__device__ __forceinline__ void cpa4(void* s, const void* g) {
    uint32_t sa = (uint32_t)__cvta_generic_to_shared(s);
    asm volatile("cp.async.ca.shared.global [%0], [%1], 4;" :: "r"(sa), "l"(g));
}

// ============================ K1: precompute ================================
// [BT,64] @ [64,192] -> Y1|Y2. K-pair packed FFMA2; W^T in smem (pad 68).
// 256 thr: cg = tid>>3 (32 col-groups, cols {2(cg+32j)..+1}, j=0..2),
//          rsub = tid&7 (rows rr*8+rsub, rr=0..5). Tile = 48 rows.
#define PT 256
#define PGRID 296
#define PTILE_R 48
#define NT_P ((BT_ + PTILE_R - 1) / PTILE_R)   // 8534

struct PSmem {
    float wt[192 * 68];            // W transposed [col][k], pad 68
    float sx[3][PTILE_R][64];      // x tile, triple buffer
};
#define PSMEM_BYTES ((int)sizeof(PSmem))

__global__ __launch_bounds__(PT, 2)
void pre_kernel(const float* __restrict__ x,   // [BT, 64]
                const float* __restrict__ gk,  // [128,128]
                const float* __restrict__ gb,
                const float* __restrict__ ck,  // [128,64]
                const float* __restrict__ cb)
{
    extern __shared__ char praw[];
    PSmem* S = reinterpret_cast<PSmem*>(praw);
    const int tid  = threadIdx.x;
    const int cg   = tid >> 3;   // 0..31
    const int rsub = tid & 7;    // 0..7

    // Load W transposed into smem (one-time)
    for (int idx = tid; idx < 192 * 64; idx += PT) {
        int col = idx >> 6, k = idx & 63;
        float v = (col < 128) ? gk[k * 128 + col] : ck[k * 64 + (col - 128)];
        S->wt[col * 68 + k] = v;
    }
    float bias[3][2];
#pragma unroll
    for (int j = 0; j < 3; j++) {
        int c0 = 2 * (cg + 32 * j);
        if (c0 < 128) { bias[j][0] = gb[c0];       bias[j][1] = gb[c0 + 1]; }
        else          { bias[j][0] = cb[c0 - 128]; bias[j][1] = cb[c0 - 127]; }
    }

    auto prefetch = [&](int tl, int bb) {
#pragma unroll
        for (int i = 0; i < 3; i++) {
            int idx   = tid + i * PT;           // 768 float4s per tile
            int row_l = idx >> 4, q = idx & 15;
            int grow  = tl * PTILE_R + row_l;
            if (grow > BT_ - 1) grow = BT_ - 1;
            cpa16(&S->sx[bb][row_l][q * 4], &x[(size_t)grow * 64 + q * 4]);
        }
        asm volatile("cp.async.commit_group;");
    };

    // Prologue: two tiles in flight
    {
        int t0 = blockIdx.x;
        if (t0 < NT_P) prefetch(t0, 0);
        else asm volatile("cp.async.commit_group;");
        int t1 = t0 + PGRID;
        if (t1 < NT_P) prefetch(t1, 1);
        else asm volatile("cp.async.commit_group;");
    }

    int i = 0;
    for (int tile = blockIdx.x; tile < NT_P; tile += PGRID, i++) {
        asm volatile("cp.async.wait_group 1;");
        __syncthreads();
        {
            int pf = tile + 2 * PGRID;
            if (pf < NT_P) prefetch(pf, (i + 2) % 3);
            else asm volatile("cp.async.commit_group;");
        }
        const int buf = i % 3;

        ull acc[6][3][2];
#pragma unroll
        for (int rr = 0; rr < 6; rr++)
#pragma unroll
            for (int j = 0; j < 3; j++)
                { acc[rr][j][0] = 0ull; acc[rr][j][1] = 0ull; }

#pragma unroll 4
        for (int kk = 0; kk < 16; kk++) {
            // weight k-runs for this thread's 6 cols (quarter-warp broadcast)
            ull wk[3][2][2];
#pragma unroll
            for (int j = 0; j < 3; j++)
#pragma unroll
                for (int h = 0; h < 2; h++) {
                    int c = 2 * (cg + 32 * j) + h;
                    ulonglong2 wv =
                        *(const ulonglong2*)&S->wt[c * 68 + 4 * kk];
                    wk[j][h][0] = wv.x; wk[j][h][1] = wv.y;
                }
#pragma unroll
            for (int rr = 0; rr < 6; rr++) {
                ulonglong2 xv =
                    *(const ulonglong2*)&S->sx[buf][rr * 8 + rsub][4 * kk];
#pragma unroll
                for (int j = 0; j < 3; j++)
#pragma unroll
                    for (int h = 0; h < 2; h++) {
                        acc[rr][j][h] = ffma2(wk[j][h][0], xv.x, acc[rr][j][h]);
                        acc[rr][j][h] = ffma2(wk[j][h][1], xv.y, acc[rr][j][h]);
                    }
            }
        }

        // Epilogue: horizontal add + bias, store
#pragma unroll
        for (int rr = 0; rr < 6; rr++) {
            int grow = tile * PTILE_R + rr * 8 + rsub;
            if (grow < BT_) {
#pragma unroll
                for (int j = 0; j < 2; j++) {
                    float2 o;
                    o.x = hadd2(acc[rr][j][0]) + bias[j][0];
                    o.y = hadd2(acc[rr][j][1]) + bias[j][1];
                    *(float2*)&Y1g[(size_t)grow * 128 + 2 * (cg + 32 * j)] = o;
                }
                float2 o2;
                o2.x = hadd2(acc[rr][2][0]) + bias[2][0];
                o2.y = hadd2(acc[rr][2][1]) + bias[2][1];
                *(float2*)&Y2g[(size_t)grow * 64 + 2 * cg] = o2;
            }
        }
    }
    asm volatile("cp.async.wait_group 0;");
}

// ============================ K2: recurrence (R7 + tree adds) ===============
#define M_ 7
#define RTHREADS 256
#define NCTA_R ((B_ + M_ - 1) / M_)   // 293

struct RSmem {
    float sy1[3][M_][128];
    float sy2[3][M_][64];
    float sh[M_][64];
    float srh[M_][64];
    float psg[4 * M_ * 128];
    float psc[8 * M_ * 64];
    float sa[3][8];
    int   sl[8];
};
#define RSMEM_BYTES ((int)sizeof(RSmem))

__global__ __launch_bounds__(RTHREADS, 2)
void augru_rec(const int*   __restrict__ slen_g,
               const float* __restrict__ att,
               const float* __restrict__ gk,
               const float* __restrict__ ck,
               float*       __restrict__ out)
{
    extern __shared__ char smem_raw[];
    RSmem* S = reinterpret_cast<RSmem*>(smem_raw);

    const int tid = threadIdx.x;
    const int b0  = blockIdx.x * M_;

    const int gng = tid & 63;
    const int gks = tid >> 6;
    const int cng = tid & 31;
    const int cks = tid >> 5;

    ull wg2[8][2];
#pragma unroll
    for (int kp = 0; kp < 8; kp++) {
        int k = 64 + gks * 16 + 2 * kp;
#pragma unroll
        for (int c = 0; c < 2; c++)
            wg2[kp][c] = pack2(gk[k * 128 + 2 * gng + c],
                               gk[(k + 1) * 128 + 2 * gng + c]);
    }
    ull wc2[4][2];
#pragma unroll
    for (int kp = 0; kp < 4; kp++) {
        int k = 64 + cks * 8 + 2 * kp;
#pragma unroll
        for (int c = 0; c < 2; c++)
            wc2[kp][c] = pack2(ck[k * 64 + 2 * cng + c],
                               ck[(k + 1) * 64 + 2 * cng + c]);
    }

    for (int idx = tid; idx < M_ * 64; idx += RTHREADS)
        (&S->sh[0][0])[idx] = 0.0f;
    if (tid < M_) {
        int b = b0 + tid; if (b >= B_) b = B_ - 1;
        S->sl[tid] = slen_g[b];
    }

    const int y1m = tid >> 5, y1q = tid & 31;
    const int y2m = tid >> 4, y2q = tid & 15;
    int by1 = b0 + y1m; if (by1 >= B_) by1 = B_ - 1;
    int by2 = b0 + y2m; if (by2 >= B_) by2 = B_ - 1;
    int ba  = b0 + tid; if (ba  >= B_) ba  = B_ - 1;

    auto do_prefetch = [&](int tt, int bb) {
        if (tid < 224)
            cpa16((char*)&S->sy1[bb][0][0] + tid * 16,
                  &Y1g[((size_t)by1 * T_ + tt) * 128 + y1q * 4]);
        if (tid < 112)
            cpa16((char*)&S->sy2[bb][0][0] + tid * 16,
                  &Y2g[((size_t)by2 * T_ + tt) * 64 + y2q * 4]);
        if (tid < M_)
            cpa4(&S->sa[bb][tid], &att[ba * T_ + tt]);
        asm volatile("cp.async.commit_group;");
    };

    do_prefetch(0, 0);
    do_prefetch(1 < T_ ? 1 : 0, 1);
    asm volatile("cp.async.wait_group 1;");
    __syncthreads();

    for (int t = 0; t < T_; ++t) {
        const int buf = t % 3;
        {
            int tn = (t + 2 < T_) ? t + 2 : T_ - 1;
            do_prefetch(tn, (t + 2) % 3);
        }

        // ---- Phase A: gate h-GEMM partials -> psg
#pragma unroll
        for (int mh = 0; mh < 2; mh++) {
            const int mbase = mh * 4;
            const int mcnt  = mh ? 3 : 4;
            ull acc[4][2];
#pragma unroll
            for (int mm = 0; mm < 4; mm++)
                { acc[mm][0] = 0ull; acc[mm][1] = 0ull; }
#pragma unroll
            for (int mm = 0; mm < 4; mm++) {
                if (mm >= mcnt) break;
                const ulonglong2* p =
                    (const ulonglong2*)&S->sh[mbase + mm][gks * 16];
                ulonglong2 v0 = p[0], v1 = p[1], v2 = p[2], v3 = p[3];
#pragma unroll
                for (int c = 0; c < 2; c++) {
                    acc[mm][c] = ffma2(wg2[0][c], v0.x, acc[mm][c]);
                    acc[mm][c] = ffma2(wg2[1][c], v0.y, acc[mm][c]);
                    acc[mm][c] = ffma2(wg2[2][c], v1.x, acc[mm][c]);
                    acc[mm][c] = ffma2(wg2[3][c], v1.y, acc[mm][c]);
                    acc[mm][c] = ffma2(wg2[4][c], v2.x, acc[mm][c]);
                    acc[mm][c] = ffma2(wg2[5][c], v2.y, acc[mm][c]);
                    acc[mm][c] = ffma2(wg2[6][c], v3.x, acc[mm][c]);
                    acc[mm][c] = ffma2(wg2[7][c], v3.y, acc[mm][c]);
                }
            }
#pragma unroll
            for (int mm = 0; mm < 4; mm++) {
                if (mm >= mcnt) break;
                *(float2*)&S->psg[(gks * M_ + mbase + mm) * 128 + 2 * gng] =
                    make_float2(hadd2(acc[mm][0]), hadd2(acc[mm][1]));
            }
        }
        __syncthreads();

        // ---- Phase B: r-gate finalize (tree adds) -> srh
        if (tid < M_ * 32) {
            int m = tid >> 5, n0 = (tid & 31) * 2;
            ull p0 = *(const ull*)&S->psg[(0 * M_ + m) * 128 + n0];
            ull p1 = *(const ull*)&S->psg[(1 * M_ + m) * 128 + n0];
            ull p2 = *(const ull*)&S->psg[(2 * M_ + m) * 128 + n0];
            ull p3 = *(const ull*)&S->psg[(3 * M_ + m) * 128 + n0];
            ull y  = *(const ull*)&S->sy1[buf][m][n0];
            ull s  = add2(add2(p0, p1), add2(p2, p3));
            s = add2(s, y);
            float g0, g1; unpack2(s, g0, g1);
            g0 = sigmoid_f(g0); g1 = sigmoid_f(g1);
            float2 hv = *(const float2*)&S->sh[m][n0];
            *(float2*)&S->srh[m][n0] = make_float2(g0 * hv.x, g1 * hv.y);
        }
        __syncthreads();

        // ---- Phase C: cand rh-GEMM partials -> psc
#pragma unroll
        for (int mh = 0; mh < 2; mh++) {
            const int mbase = mh * 4;
            const int mcnt  = mh ? 3 : 4;
            ull acc[4][2];
#pragma unroll
            for (int mm = 0; mm < 4; mm++)
                { acc[mm][0] = 0ull; acc[mm][1] = 0ull; }
#pragma unroll
            for (int mm = 0; mm < 4; mm++) {
                if (mm >= mcnt) break;
                const ulonglong2* p =
                    (const ulonglong2*)&S->srh[mbase + mm][cks * 8];
                ulonglong2 v0 = p[0], v1 = p[1];
#pragma unroll
                for (int c = 0; c < 2; c++) {
                    acc[mm][c] = ffma2(wc2[0][c], v0.x, acc[mm][c]);
                    acc[mm][c] = ffma2(wc2[1][c], v0.y, acc[mm][c]);
                    acc[mm][c] = ffma2(wc2[2][c], v1.x, acc[mm][c]);
                    acc[mm][c] = ffma2(wc2[3][c], v1.y, acc[mm][c]);
                }
            }
#pragma unroll
            for (int mm = 0; mm < 4; mm++) {
                if (mm >= mcnt) break;
                *(float2*)&S->psc[(cks * M_ + mbase + mm) * 64 + 2 * cng] =
                    make_float2(hadd2(acc[mm][0]), hadd2(acc[mm][1]));
            }
        }
        __syncthreads();

        // ---- Phase D: u-gate + cand finalize (tree adds) + update + output
        if (tid < M_ * 32) {
            int m = tid >> 5, n0 = (tid & 31) * 2;
            // u-gate
            ull q0 = *(const ull*)&S->psg[(0 * M_ + m) * 128 + 64 + n0];
            ull q1 = *(const ull*)&S->psg[(1 * M_ + m) * 128 + 64 + n0];
            ull q2 = *(const ull*)&S->psg[(2 * M_ + m) * 128 + 64 + n0];
            ull q3 = *(const ull*)&S->psg[(3 * M_ + m) * 128 + 64 + n0];
            ull su_ = add2(add2(q0, q1), add2(q2, q3));
            su_ = add2(su_, *(const ull*)&S->sy1[buf][m][64 + n0]);
            float u0, u1; unpack2(su_, u0, u1);
            u0 = sigmoid_f(u0); u1 = sigmoid_f(u1);
            // candidate (8 partials, tree)
            ull c0_ = *(const ull*)&S->psc[(0 * M_ + m) * 64 + n0];
            ull c1_ = *(const ull*)&S->psc[(1 * M_ + m) * 64 + n0];
            ull c2_ = *(const ull*)&S->psc[(2 * M_ + m) * 64 + n0];
            ull c3_ = *(const ull*)&S->psc[(3 * M_ + m) * 64 + n0];
            ull c4_ = *(const ull*)&S->psc[(4 * M_ + m) * 64 + n0];
            ull c5_ = *(const ull*)&S->psc[(5 * M_ + m) * 64 + n0];
            ull c6_ = *(const ull*)&S->psc[(6 * M_ + m) * 64 + n0];
            ull c7_ = *(const ull*)&S->psc[(7 * M_ + m) * 64 + n0];
            ull sc_ = add2(add2(add2(c0_, c1_), add2(c2_, c3_)),
                           add2(add2(c4_, c5_), add2(c6_, c7_)));
            sc_ = add2(sc_, *(const ull*)&S->sy2[buf][m][n0]);
            float c0, c1; unpack2(sc_, c0, c1);
            c0 = tanh_f(c0); c1 = tanh_f(c1);
            // update
            float2 hv = *(const float2*)&S->sh[m][n0];
            float a   = S->sa[buf][m];
            float uh0 = (1.0f - a) * u0;
            float uh1 = (1.0f - a) * u1;
            float hn0 = uh0 * hv.x + (1.0f - uh0) * c0;
            float hn1 = uh1 * hv.y + (1.0f - uh1) * c1;
            bool valid = (t < S->sl[m]);
            *(float2*)&S->sh[m][n0] =
                make_float2(valid ? hn0 : hv.x, valid ? hn1 : hv.y);
            int b = b0 + m;
            if (b < B_)
                *(float2*)&out[((size_t)b * T_ + t) * 64 + n0] =
                    make_float2(valid ? hn0 : 0.0f, valid ? hn1 : 0.0f);
        }
        asm volatile("cp.async.wait_group 1;");
        __syncthreads();
    }
    asm volatile("cp.async.wait_group 0;");
}

extern "C" void kernel_launch(void* const* d_in, const int* in_sizes, int n_in,
                              void* d_out, int out_size) {
    const float* x   = (const float*)d_in[0];
    const int*   sl  = (const int*)  d_in[1];
    const float* att = (const float*)d_in[2];
    const float* gk  = (const float*)d_in[3];
    const float* gb  = (const float*)d_in[4];
    const float* ck  = (const float*)d_in[5];
    const float* cb  = (const float*)d_in[6];
    float* out = (float*)d_out;

    cudaFuncSetAttribute(pre_kernel,
                         cudaFuncAttributeMaxDynamicSharedMemorySize, PSMEM_BYTES);
    pre_kernel<<<PGRID, PT, PSMEM_BYTES>>>(x, gk, gb, ck, cb);

    cudaFuncSetAttribute(augru_rec,
                         cudaFuncAttributeMaxDynamicSharedMemorySize, RSMEM_BYTES);
    augru_rec<<<NCTA_R, RTHREADS, RSMEM_BYTES>>>(sl, att, gk, ck, out);
}

// round 9
// speedup vs baseline: 1.5986x; 1.5986x over previous
#include <cuda_runtime.h>
#include <cstdint>

// AUGRU, B=2048, T=200, D=H=64 — SINGLE fused persistent kernel.
// Each CTA owns M=7 batch rows, runs all T=200 steps. The non-recurrent
// x-projection Y(t) = x(t)@[Wgx|Wcx]+bias is computed IN-CTA two steps
// ahead (phase X, k-quad-packed FFMA2, W in smem), filling idle issue
// slots of the recurrence phases. No global Y scratch at all.

#define B_ 2048
#define T_ 200
#define D_ 64
#define H_ 64

typedef unsigned long long ull;

__device__ __forceinline__ ull pack2(float lo, float hi) {
    ull r; asm("mov.b64 %0, {%1, %2};" : "=l"(r) : "f"(lo), "f"(hi)); return r;
}
__device__ __forceinline__ void unpack2(ull v, float& lo, float& hi) {
    asm("mov.b64 {%0, %1}, %2;" : "=f"(lo), "=f"(hi) : "l"(v));
}
__device__ __forceinline__ ull ffma2(ull a, ull b, ull c) {
    ull d; asm("fma.rn.f32x2 %0, %1, %2, %3;" : "=l"(d) : "l"(a), "l"(b), "l"(c)); return d;
}
__device__ __forceinline__ ull add2(ull a, ull b) {
    ull d; asm("add.rn.f32x2 %0, %1, %2;" : "=l"(d) : "l"(a), "l"(b)); return d;
}
__device__ __forceinline__ float hadd2(ull v) {
    float lo, hi; unpack2(v, lo, hi); return lo + hi;
}
__device__ __forceinline__ float sigmoid_f(float x) {
    return __fdividef(1.0f, 1.0f + __expf(-x));
}
__device__ __forceinline__ float tanh_f(float x) {
    float e = __expf(2.0f * x);
    return 1.0f - __fdividef(2.0f, e + 1.0f);
}
__device__ __forceinline__ void cpa16(void* s, const void* g) {
    uint32_t sa = (uint32_t)__cvta_generic_to_shared(s);
    asm volatile("cp.async.ca.shared.global [%0], [%1], 16;" :: "r"(sa), "l"(g));
}
__device__ __forceinline__ void cpa4(void* s, const void* g) {
    uint32_t sa = (uint32_t)__cvta_generic_to_shared(s);
    asm volatile("cp.async.ca.shared.global [%0], [%1], 4;" :: "r"(sa), "l"(g));
}

#define M_ 7
#define RTHREADS 256
#define NCTA_R ((B_ + M_ - 1) / M_)   // 293

struct RSmem {
    ull   wt4[16 * 192 * 2];   // k-quad packed W^T for x-proj: [(kk*192+c)*2+{0,1}]
    float sy1[3][M_][128];     // Y gate ring
    float sy2[3][M_][64];      // Y cand ring
    float sx[3][M_][64];       // x ring
    float sh[M_][64];
    float srh[M_][64];
    float psg[4 * M_ * 128];
    float psc[8 * M_ * 64];
    float sa[4][8];
    int   sl[8];
};
#define RSMEM_BYTES ((int)sizeof(RSmem))

__global__ __launch_bounds__(RTHREADS, 2)
void augru_fused(const float* __restrict__ x,      // [B,T,64]
                 const int*   __restrict__ slen_g, // [B]
                 const float* __restrict__ att,    // [B,T]
                 const float* __restrict__ gk,     // [128,128]
                 const float* __restrict__ gb,     // [128]
                 const float* __restrict__ ck,     // [128,64]
                 const float* __restrict__ cb,     // [64]
                 float*       __restrict__ out)    // [B,T,64]
{
    extern __shared__ char smem_raw[];
    RSmem* S = reinterpret_cast<RSmem*>(smem_raw);

    const int tid = threadIdx.x;
    const int b0  = blockIdx.x * M_;

    // ---- recurrent-GEMM thread mappings (R7/R8 proven) ----
    const int gng = tid & 63;   // gate: 64 col-pairs x 4 k-slices
    const int gks = tid >> 6;
    const int cng = tid & 31;   // cand: 32 col-pairs x 8 k-slices
    const int cks = tid >> 5;

    ull wg2[8][2];
#pragma unroll
    for (int kp = 0; kp < 8; kp++) {
        int k = 64 + gks * 16 + 2 * kp;
#pragma unroll
        for (int c = 0; c < 2; c++)
            wg2[kp][c] = pack2(gk[k * 128 + 2 * gng + c],
                               gk[(k + 1) * 128 + 2 * gng + c]);
    }
    ull wc2[4][2];
#pragma unroll
    for (int kp = 0; kp < 4; kp++) {
        int k = 64 + cks * 8 + 2 * kp;
#pragma unroll
        for (int c = 0; c < 2; c++)
            wc2[kp][c] = pack2(ck[k * 64 + 2 * cng + c],
                               ck[(k + 1) * 64 + 2 * cng + c]);
    }

    // ---- phase-X mapping: 3 cols {xcg, xcg+64, xcg+128}, rows {xrs, xrs+4} ----
    const int xcg = tid & 63;
    const int xrs = tid >> 6;         // 0..3 (xrs==3: single row 3)
    float biasx[3];
    biasx[0] = gb[xcg];
    biasx[1] = gb[xcg + 64];
    biasx[2] = cb[xcg];

    // ---- one-time smem init ----
    // W^T k-quad packed (x-half rows k=0..63 of both weight matrices)
    for (int idx = tid; idx < 16 * 192; idx += RTHREADS) {
        int kk = idx / 192, c = idx % 192;
        int k = 4 * kk;
        float w0, w1, w2, w3;
        if (c < 128) {
            w0 = gk[k * 128 + c];       w1 = gk[(k + 1) * 128 + c];
            w2 = gk[(k + 2) * 128 + c]; w3 = gk[(k + 3) * 128 + c];
        } else {
            int cc = c - 128;
            w0 = ck[k * 64 + cc];       w1 = ck[(k + 1) * 64 + cc];
            w2 = ck[(k + 2) * 64 + cc]; w3 = ck[(k + 3) * 64 + cc];
        }
        S->wt4[idx * 2]     = pack2(w0, w1);
        S->wt4[idx * 2 + 1] = pack2(w2, w3);
    }
    for (int idx = tid; idx < M_ * 64; idx += RTHREADS)
        (&S->sh[0][0])[idx] = 0.0f;
    if (tid < M_) {
        int b = b0 + tid; if (b >= B_) b = B_ - 1;
        S->sl[tid] = slen_g[b];
    }

    // ---- async input fetch helpers ----
    const int xrow = tid >> 4, xq = tid & 15;     // tid<112: x tile float4s
    int bxr = b0 + xrow; if (bxr >= B_) bxr = B_ - 1;
    int ba  = b0 + tid;  if (ba  >= B_) ba  = B_ - 1;

    auto fetch_step = [&](int tt, int bx, int batt) {
        if (tid < M_ * 16)
            cpa16(&S->sx[bx][xrow][xq * 4],
                  &x[((size_t)bxr * T_ + tt) * 64 + xq * 4]);
        if (tid < M_)
            cpa4(&S->sa[batt][tid], &att[(size_t)ba * T_ + tt]);
        asm volatile("cp.async.commit_group;");
    };

    // ---- phase X: Y(idx) = x@Wx + bias, sx[idx] -> sy1/sy2[idx] ----
    auto xproj = [&](int idx) {
        ull acc[3][2];
#pragma unroll
        for (int j = 0; j < 3; j++) { acc[j][0] = 0ull; acc[j][1] = 0ull; }
        const int r0 = xrs, r1 = (xrs < 3) ? xrs + 4 : xrs;
#pragma unroll
        for (int kk = 0; kk < 16; kk++) {
            ulonglong2 w0 = *(const ulonglong2*)&S->wt4[(kk * 192 + xcg) * 2];
            ulonglong2 w1 = *(const ulonglong2*)&S->wt4[(kk * 192 + xcg + 64) * 2];
            ulonglong2 w2 = *(const ulonglong2*)&S->wt4[(kk * 192 + xcg + 128) * 2];
            ulonglong2 xa = *(const ulonglong2*)&S->sx[idx][r0][4 * kk];
            ulonglong2 xb = *(const ulonglong2*)&S->sx[idx][r1][4 * kk];
            acc[0][0] = ffma2(w0.x, xa.x, acc[0][0]);
            acc[0][0] = ffma2(w0.y, xa.y, acc[0][0]);
            acc[1][0] = ffma2(w1.x, xa.x, acc[1][0]);
            acc[1][0] = ffma2(w1.y, xa.y, acc[1][0]);
            acc[2][0] = ffma2(w2.x, xa.x, acc[2][0]);
            acc[2][0] = ffma2(w2.y, xa.y, acc[2][0]);
            acc[0][1] = ffma2(w0.x, xb.x, acc[0][1]);
            acc[0][1] = ffma2(w0.y, xb.y, acc[0][1]);
            acc[1][1] = ffma2(w1.x, xb.x, acc[1][1]);
            acc[1][1] = ffma2(w1.y, xb.y, acc[1][1]);
            acc[2][1] = ffma2(w2.x, xb.x, acc[2][1]);
            acc[2][1] = ffma2(w2.y, xb.y, acc[2][1]);
        }
        // store (lanes consecutive xcg -> conflict-free)
        S->sy1[idx][r0][xcg]      = hadd2(acc[0][0]) + biasx[0];
        S->sy1[idx][r0][xcg + 64] = hadd2(acc[1][0]) + biasx[1];
        S->sy2[idx][r0][xcg]      = hadd2(acc[2][0]) + biasx[2];
        if (xrs < 3) {
            S->sy1[idx][r1][xcg]      = hadd2(acc[0][1]) + biasx[0];
            S->sy1[idx][r1][xcg + 64] = hadd2(acc[1][1]) + biasx[1];
            S->sy2[idx][r1][xcg]      = hadd2(acc[2][1]) + biasx[2];
        }
    };

    // ---- prologue: fetch x(0..2)/att(0..2), compute Y(0), Y(1) ----
    fetch_step(0, 0, 0);
    fetch_step(1 < T_ ? 1 : 0, 1, 1);
    fetch_step(2 < T_ ? 2 : 0, 2, 2);
    asm volatile("cp.async.wait_group 0;");
    __syncthreads();          // x tiles + wt4 + sh visible
    xproj(0);
    if (1 < T_) xproj(1);
    __syncthreads();

    // ---- main T loop ----
    for (int t = 0; t < T_; ++t) {
        const int buf = t % 3;
        {
            int tn = (t + 3 < T_) ? t + 3 : T_ - 1;
            fetch_step(tn, (t + 3) % 3, (t + 3) & 3);
        }

        // ---- Phase A: gate h-GEMM partials -> psg
#pragma unroll
        for (int mh = 0; mh < 2; mh++) {
            const int mbase = mh * 4;
            const int mcnt  = mh ? 3 : 4;
            ull acc[4][2];
#pragma unroll
            for (int mm = 0; mm < 4; mm++)
                { acc[mm][0] = 0ull; acc[mm][1] = 0ull; }
#pragma unroll
            for (int mm = 0; mm < 4; mm++) {
                if (mm >= mcnt) break;
                const ulonglong2* p =
                    (const ulonglong2*)&S->sh[mbase + mm][gks * 16];
                ulonglong2 v0 = p[0], v1 = p[1], v2 = p[2], v3 = p[3];
#pragma unroll
                for (int c = 0; c < 2; c++) {
                    acc[mm][c] = ffma2(wg2[0][c], v0.x, acc[mm][c]);
                    acc[mm][c] = ffma2(wg2[1][c], v0.y, acc[mm][c]);
                    acc[mm][c] = ffma2(wg2[2][c], v1.x, acc[mm][c]);
                    acc[mm][c] = ffma2(wg2[3][c], v1.y, acc[mm][c]);
                    acc[mm][c] = ffma2(wg2[4][c], v2.x, acc[mm][c]);
                    acc[mm][c] = ffma2(wg2[5][c], v2.y, acc[mm][c]);
                    acc[mm][c] = ffma2(wg2[6][c], v3.x, acc[mm][c]);
                    acc[mm][c] = ffma2(wg2[7][c], v3.y, acc[mm][c]);
                }
            }
#pragma unroll
            for (int mm = 0; mm < 4; mm++) {
                if (mm >= mcnt) break;
                *(float2*)&S->psg[(gks * M_ + mbase + mm) * 128 + 2 * gng] =
                    make_float2(hadd2(acc[mm][0]), hadd2(acc[mm][1]));
            }
        }
        __syncthreads();

        // ---- Phase B: r-gate finalize -> srh  |  Phase X: Y(t+2)
        if (tid < M_ * 32) {
            int m = tid >> 5, n0 = (tid & 31) * 2;
            ull p0 = *(const ull*)&S->psg[(0 * M_ + m) * 128 + n0];
            ull p1 = *(const ull*)&S->psg[(1 * M_ + m) * 128 + n0];
            ull p2 = *(const ull*)&S->psg[(2 * M_ + m) * 128 + n0];
            ull p3 = *(const ull*)&S->psg[(3 * M_ + m) * 128 + n0];
            ull s  = add2(add2(p0, p1), add2(p2, p3));
            s = add2(s, *(const ull*)&S->sy1[buf][m][n0]);
            float g0, g1; unpack2(s, g0, g1);
            g0 = sigmoid_f(g0); g1 = sigmoid_f(g1);
            float2 hv = *(const float2*)&S->sh[m][n0];
            *(float2*)&S->srh[m][n0] = make_float2(g0 * hv.x, g1 * hv.y);
        }
        if (t + 2 < T_) xproj((t + 2) % 3);
        __syncthreads();

        // ---- Phase C: cand rh-GEMM partials -> psc
#pragma unroll
        for (int mh = 0; mh < 2; mh++) {
            const int mbase = mh * 4;
            const int mcnt  = mh ? 3 : 4;
            ull acc[4][2];
#pragma unroll
            for (int mm = 0; mm < 4; mm++)
                { acc[mm][0] = 0ull; acc[mm][1] = 0ull; }
#pragma unroll
            for (int mm = 0; mm < 4; mm++) {
                if (mm >= mcnt) break;
                const ulonglong2* p =
                    (const ulonglong2*)&S->srh[mbase + mm][cks * 8];
                ulonglong2 v0 = p[0], v1 = p[1];
#pragma unroll
                for (int c = 0; c < 2; c++) {
                    acc[mm][c] = ffma2(wc2[0][c], v0.x, acc[mm][c]);
                    acc[mm][c] = ffma2(wc2[1][c], v0.y, acc[mm][c]);
                    acc[mm][c] = ffma2(wc2[2][c], v1.x, acc[mm][c]);
                    acc[mm][c] = ffma2(wc2[3][c], v1.y, acc[mm][c]);
                }
            }
#pragma unroll
            for (int mm = 0; mm < 4; mm++) {
                if (mm >= mcnt) break;
                *(float2*)&S->psc[(cks * M_ + mbase + mm) * 64 + 2 * cng] =
                    make_float2(hadd2(acc[mm][0]), hadd2(acc[mm][1]));
            }
        }
        __syncthreads();

        // ---- Phase D: u-gate + cand finalize + h update + output
        if (tid < M_ * 32) {
            int m = tid >> 5, n0 = (tid & 31) * 2;
            ull q0 = *(const ull*)&S->psg[(0 * M_ + m) * 128 + 64 + n0];
            ull q1 = *(const ull*)&S->psg[(1 * M_ + m) * 128 + 64 + n0];
            ull q2 = *(const ull*)&S->psg[(2 * M_ + m) * 128 + 64 + n0];
            ull q3 = *(const ull*)&S->psg[(3 * M_ + m) * 128 + 64 + n0];
            ull su_ = add2(add2(q0, q1), add2(q2, q3));
            su_ = add2(su_, *(const ull*)&S->sy1[buf][m][64 + n0]);
            float u0, u1; unpack2(su_, u0, u1);
            u0 = sigmoid_f(u0); u1 = sigmoid_f(u1);
            ull c0_ = *(const ull*)&S->psc[(0 * M_ + m) * 64 + n0];
            ull c1_ = *(const ull*)&S->psc[(1 * M_ + m) * 64 + n0];
            ull c2_ = *(const ull*)&S->psc[(2 * M_ + m) * 64 + n0];
            ull c3_ = *(const ull*)&S->psc[(3 * M_ + m) * 64 + n0];
            ull c4_ = *(const ull*)&S->psc[(4 * M_ + m) * 64 + n0];
            ull c5_ = *(const ull*)&S->psc[(5 * M_ + m) * 64 + n0];
            ull c6_ = *(const ull*)&S->psc[(6 * M_ + m) * 64 + n0];
            ull c7_ = *(const ull*)&S->psc[(7 * M_ + m) * 64 + n0];
            ull sc_ = add2(add2(add2(c0_, c1_), add2(c2_, c3_)),
                           add2(add2(c4_, c5_), add2(c6_, c7_)));
            sc_ = add2(sc_, *(const ull*)&S->sy2[buf][m][n0]);
            float c0, c1; unpack2(sc_, c0, c1);
            c0 = tanh_f(c0); c1 = tanh_f(c1);
            float2 hv = *(const float2*)&S->sh[m][n0];
            float a   = S->sa[t & 3][m];
            float uh0 = (1.0f - a) * u0;
            float uh1 = (1.0f - a) * u1;
            float hn0 = uh0 * hv.x + (1.0f - uh0) * c0;
            float hn1 = uh1 * hv.y + (1.0f - uh1) * c1;
            bool valid = (t < S->sl[m]);
            *(float2*)&S->sh[m][n0] =
                make_float2(valid ? hn0 : hv.x, valid ? hn1 : hv.y);
            int b = b0 + m;
            if (b < B_)
                *(float2*)&out[((size_t)b * T_ + t) * 64 + n0] =
                    make_float2(valid ? hn0 : 0.0f, valid ? hn1 : 0.0f);
        }
        asm volatile("cp.async.wait_group 0;");
        __syncthreads();
    }
}

extern "C" void kernel_launch(void* const* d_in, const int* in_sizes, int n_in,
                              void* d_out, int out_size) {
    const float* x   = (const float*)d_in[0];
    const int*   sl  = (const int*)  d_in[1];
    const float* att = (const float*)d_in[2];
    const float* gk  = (const float*)d_in[3];
    const float* gb  = (const float*)d_in[4];
    const float* ck  = (const float*)d_in[5];
    const float* cb  = (const float*)d_in[6];
    float* out = (float*)d_out;

    cudaFuncSetAttribute(augru_fused,
                         cudaFuncAttributeMaxDynamicSharedMemorySize, RSMEM_BYTES);
    augru_fused<<<NCTA_R, RTHREADS, RSMEM_BYTES>>>(x, sl, att, gk, gb, ck, cb, out);
}

// round 10
// speedup vs baseline: 2.1189x; 1.3255x over previous
#include <cuda_runtime.h>
#include <cstdint>

// AUGRU, B=2048, T=200, D=H=64. Two-kernel split (fusion rejected in R9).
//  K1 (pre): Y1 = x@Wgx + gb [BT,128], Y2 = x@Wcx + cb [BT,64].
//            W in smem (row-major, broadcast-friendly LDS.64 col-pairs),
//            32-row tiles, 3 CTAs/SM, depth-2 cp.async, f32x2 col-pair accs.
//  K2 (rec): R8 recurrence verbatim (measured 353us): M=7, 256 thr,
//            2 CTAs/SM, r-only phase B, tree adds, depth-2 cp.async.

#define B_ 2048
#define T_ 200
#define D_ 64
#define H_ 64
#define BT_ (B_ * T_)

typedef unsigned long long ull;

__device__ float Y1g[BT_ * 128];
__device__ float Y2g[BT_ * 64];

__device__ __forceinline__ ull pack2(float lo, float hi) {
    ull r; asm("mov.b64 %0, {%1, %2};" : "=l"(r) : "f"(lo), "f"(hi)); return r;
}
__device__ __forceinline__ void unpack2(ull v, float& lo, float& hi) {
    asm("mov.b64 {%0, %1}, %2;" : "=f"(lo), "=f"(hi) : "l"(v));
}
__device__ __forceinline__ ull ffma2(ull a, ull b, ull c) {
    ull d; asm("fma.rn.f32x2 %0, %1, %2, %3;" : "=l"(d) : "l"(a), "l"(b), "l"(c)); return d;
}
__device__ __forceinline__ ull add2(ull a, ull b) {
    ull d; asm("add.rn.f32x2 %0, %1, %2;" : "=l"(d) : "l"(a), "l"(b)); return d;
}
__device__ __forceinline__ float hadd2(ull v) {
    float lo, hi; unpack2(v, lo, hi); return lo + hi;
}
__device__ __forceinline__ float sigmoid_f(float x) {
    return __fdividef(1.0f, 1.0f + __expf(-x));
}
__device__ __forceinline__ float tanh_f(float x) {
    float e = __expf(2.0f * x);
    return 1.0f - __fdividef(2.0f, e + 1.0f);
}
__device__ __forceinline__ void cpa16(void* s, const void* g) {
    uint32_t sa = (uint32_t)__cvta_generic_to_shared(s);
    asm volatile("cp.async.ca.shared.global [%0], [%1], 16;" :: "r"(sa), "l"(g));
}
__device__ __forceinline__ void cpa4(void* s, const void* g) {
    uint32_t sa = (uint32_t)__cvta_generic_to_shared(s);
    asm volatile("cp.async.ca.shared.global [%0], [%1], 4;" :: "r"(sa), "l"(g));
}

// ============================ K1: precompute ================================
#define PT 256
#define PGRID 444
#define PTILE_R 32
#define NT_P (BT_ / PTILE_R)   // 12800 exactly

struct PSmem {
    float w[64][192];            // combined [Wgx | Wcx], k-major (row-major cols)
    float sx[3][PTILE_R][64];    // x tile, triple buffer
};
#define PSMEM_BYTES ((int)sizeof(PSmem))

__global__ __launch_bounds__(PT, 3)
void pre_kernel(const float* __restrict__ x,   // [BT, 64]
                const float* __restrict__ gk,  // [128,128]
                const float* __restrict__ gb,
                const float* __restrict__ ck,  // [128,64]
                const float* __restrict__ cb)
{
    extern __shared__ char praw[];
    PSmem* S = reinterpret_cast<PSmem*>(praw);
    const int tid = threadIdx.x;
    const int cg  = tid & 31;   // col-pairs: cols {2cg, 2cg+1} + 64j, j=0..2
    const int rg  = tid >> 5;   // rows rg*4 .. rg*4+3

    // Load combined W into smem (one-time)
    for (int idx = tid; idx < 64 * 48; idx += PT) {
        int k = idx / 48, c4 = idx % 48;
        float4 v;
        if (c4 < 32) v = ((const float4*)(gk + k * 128))[c4];
        else         v = ((const float4*)(ck + k * 64))[c4 - 32];
        ((float4*)&S->w[k][0])[c4] = v;
    }
    ull bias[3];
#pragma unroll
    for (int j = 0; j < 3; j++) {
        int c = 64 * j + 2 * cg;
        float lo = (c < 128) ? gb[c] : cb[c - 128];
        float hi = (c < 128) ? gb[c + 1] : cb[c + 1 - 128];
        bias[j] = pack2(lo, hi);
    }

    auto prefetch = [&](int tl, int bb) {
#pragma unroll
        for (int i = 0; i < 2; i++) {
            int idx = tid + i * PT;              // 512 float4 per 32-row tile
            cpa16((char*)&S->sx[bb][0][0] + idx * 16,
                  x + (size_t)tl * PTILE_R * 64 + idx * 4);
        }
        asm volatile("cp.async.commit_group;");
    };

    // Prologue: two tiles in flight
    {
        int t0 = blockIdx.x;
        if (t0 < NT_P) prefetch(t0, 0);
        else asm volatile("cp.async.commit_group;");
        int t1 = t0 + PGRID;
        if (t1 < NT_P) prefetch(t1, 1);
        else asm volatile("cp.async.commit_group;");
    }

    int i = 0;
    for (int tile = blockIdx.x; tile < NT_P; tile += PGRID, i++) {
        asm volatile("cp.async.wait_group 1;");
        __syncthreads();                         // tile (and W first iter) visible
        {
            int pf = tile + 2 * PGRID;
            if (pf < NT_P) prefetch(pf, (i + 2) % 3);
            else asm volatile("cp.async.commit_group;");
        }
        const int buf = i % 3;

        ull acc[4][3];
#pragma unroll
        for (int r = 0; r < 4; r++)
#pragma unroll
            for (int j = 0; j < 3; j++) acc[r][j] = bias[j];

#pragma unroll 4
        for (int kk = 0; kk < 16; kk++) {
            // x scalars for this thread's 4 rows, 4 k's (broadcast LDS.128)
            float xa[4][4];
#pragma unroll
            for (int r = 0; r < 4; r++) {
                float4 v = *(const float4*)&S->sx[buf][rg * 4 + r][4 * kk];
                xa[r][0] = v.x; xa[r][1] = v.y; xa[r][2] = v.z; xa[r][3] = v.w;
            }
#pragma unroll
            for (int ks = 0; ks < 4; ks++) {
                const int k = 4 * kk + ks;
                ull w0 = *(const ull*)&S->w[k][2 * cg];
                ull w1 = *(const ull*)&S->w[k][64 + 2 * cg];
                ull w2 = *(const ull*)&S->w[k][128 + 2 * cg];
#pragma unroll
                for (int r = 0; r < 4; r++) {
                    ull as = pack2(xa[r][ks], xa[r][ks]);
                    acc[r][0] = ffma2(w0, as, acc[r][0]);
                    acc[r][1] = ffma2(w1, as, acc[r][1]);
                    acc[r][2] = ffma2(w2, as, acc[r][2]);
                }
            }
        }

#pragma unroll
        for (int r = 0; r < 4; r++) {
            size_t row = (size_t)tile * PTILE_R + rg * 4 + r;
            float lo, hi;
            unpack2(acc[r][0], lo, hi);
            *(float2*)&Y1g[row * 128 + 2 * cg]      = make_float2(lo, hi);
            unpack2(acc[r][1], lo, hi);
            *(float2*)&Y1g[row * 128 + 64 + 2 * cg] = make_float2(lo, hi);
            unpack2(acc[r][2], lo, hi);
            *(float2*)&Y2g[row * 64 + 2 * cg]       = make_float2(lo, hi);
        }
        __syncthreads();                         // reads done before buf reuse
    }
    asm volatile("cp.async.wait_group 0;");
}

// ============================ K2: recurrence (R8, measured 353us) ===========
#define M_ 7
#define RTHREADS 256
#define NCTA_R ((B_ + M_ - 1) / M_)   // 293

struct RSmem {
    float sy1[3][M_][128];
    float sy2[3][M_][64];
    float sh[M_][64];
    float srh[M_][64];
    float psg[4 * M_ * 128];
    float psc[8 * M_ * 64];
    float sa[3][8];
    int   sl[8];
};
#define RSMEM_BYTES ((int)sizeof(RSmem))

__global__ __launch_bounds__(RTHREADS, 2)
void augru_rec(const int*   __restrict__ slen_g,
               const float* __restrict__ att,
               const float* __restrict__ gk,
               const float* __restrict__ ck,
               float*       __restrict__ out)
{
    extern __shared__ char smem_raw[];
    RSmem* S = reinterpret_cast<RSmem*>(smem_raw);

    const int tid = threadIdx.x;
    const int b0  = blockIdx.x * M_;

    const int gng = tid & 63;
    const int gks = tid >> 6;
    const int cng = tid & 31;
    const int cks = tid >> 5;

    ull wg2[8][2];
#pragma unroll
    for (int kp = 0; kp < 8; kp++) {
        int k = 64 + gks * 16 + 2 * kp;
#pragma unroll
        for (int c = 0; c < 2; c++)
            wg2[kp][c] = pack2(gk[k * 128 + 2 * gng + c],
                               gk[(k + 1) * 128 + 2 * gng + c]);
    }
    ull wc2[4][2];
#pragma unroll
    for (int kp = 0; kp < 4; kp++) {
        int k = 64 + cks * 8 + 2 * kp;
#pragma unroll
        for (int c = 0; c < 2; c++)
            wc2[kp][c] = pack2(ck[k * 64 + 2 * cng + c],
                               ck[(k + 1) * 64 + 2 * cng + c]);
    }

    for (int idx = tid; idx < M_ * 64; idx += RTHREADS)
        (&S->sh[0][0])[idx] = 0.0f;
    if (tid < M_) {
        int b = b0 + tid; if (b >= B_) b = B_ - 1;
        S->sl[tid] = slen_g[b];
    }

    const int y1m = tid >> 5, y1q = tid & 31;
    const int y2m = tid >> 4, y2q = tid & 15;
    int by1 = b0 + y1m; if (by1 >= B_) by1 = B_ - 1;
    int by2 = b0 + y2m; if (by2 >= B_) by2 = B_ - 1;
    int ba  = b0 + tid; if (ba  >= B_) ba  = B_ - 1;

    auto do_prefetch = [&](int tt, int bb) {
        if (tid < 224)
            cpa16((char*)&S->sy1[bb][0][0] + tid * 16,
                  &Y1g[((size_t)by1 * T_ + tt) * 128 + y1q * 4]);
        if (tid < 112)
            cpa16((char*)&S->sy2[bb][0][0] + tid * 16,
                  &Y2g[((size_t)by2 * T_ + tt) * 64 + y2q * 4]);
        if (tid < M_)
            cpa4(&S->sa[bb][tid], &att[(size_t)ba * T_ + tt]);
        asm volatile("cp.async.commit_group;");
    };

    do_prefetch(0, 0);
    do_prefetch(1 < T_ ? 1 : 0, 1);
    asm volatile("cp.async.wait_group 1;");
    __syncthreads();

    for (int t = 0; t < T_; ++t) {
        const int buf = t % 3;
        {
            int tn = (t + 2 < T_) ? t + 2 : T_ - 1;
            do_prefetch(tn, (t + 2) % 3);
        }

        // ---- Phase A: gate h-GEMM partials -> psg
#pragma unroll
        for (int mh = 0; mh < 2; mh++) {
            const int mbase = mh * 4;
            const int mcnt  = mh ? 3 : 4;
            ull acc[4][2];
#pragma unroll
            for (int mm = 0; mm < 4; mm++)
                { acc[mm][0] = 0ull; acc[mm][1] = 0ull; }
#pragma unroll
            for (int mm = 0; mm < 4; mm++) {
                if (mm >= mcnt) break;
                const ulonglong2* p =
                    (const ulonglong2*)&S->sh[mbase + mm][gks * 16];
                ulonglong2 v0 = p[0], v1 = p[1], v2 = p[2], v3 = p[3];
#pragma unroll
                for (int c = 0; c < 2; c++) {
                    acc[mm][c] = ffma2(wg2[0][c], v0.x, acc[mm][c]);
                    acc[mm][c] = ffma2(wg2[1][c], v0.y, acc[mm][c]);
                    acc[mm][c] = ffma2(wg2[2][c], v1.x, acc[mm][c]);
                    acc[mm][c] = ffma2(wg2[3][c], v1.y, acc[mm][c]);
                    acc[mm][c] = ffma2(wg2[4][c], v2.x, acc[mm][c]);
                    acc[mm][c] = ffma2(wg2[5][c], v2.y, acc[mm][c]);
                    acc[mm][c] = ffma2(wg2[6][c], v3.x, acc[mm][c]);
                    acc[mm][c] = ffma2(wg2[7][c], v3.y, acc[mm][c]);
                }
            }
#pragma unroll
            for (int mm = 0; mm < 4; mm++) {
                if (mm >= mcnt) break;
                *(float2*)&S->psg[(gks * M_ + mbase + mm) * 128 + 2 * gng] =
                    make_float2(hadd2(acc[mm][0]), hadd2(acc[mm][1]));
            }
        }
        __syncthreads();

        // ---- Phase B: r-gate finalize (tree adds) -> srh
        if (tid < M_ * 32) {
            int m = tid >> 5, n0 = (tid & 31) * 2;
            ull p0 = *(const ull*)&S->psg[(0 * M_ + m) * 128 + n0];
            ull p1 = *(const ull*)&S->psg[(1 * M_ + m) * 128 + n0];
            ull p2 = *(const ull*)&S->psg[(2 * M_ + m) * 128 + n0];
            ull p3 = *(const ull*)&S->psg[(3 * M_ + m) * 128 + n0];
            ull s  = add2(add2(p0, p1), add2(p2, p3));
            s = add2(s, *(const ull*)&S->sy1[buf][m][n0]);
            float g0, g1; unpack2(s, g0, g1);
            g0 = sigmoid_f(g0); g1 = sigmoid_f(g1);
            float2 hv = *(const float2*)&S->sh[m][n0];
            *(float2*)&S->srh[m][n0] = make_float2(g0 * hv.x, g1 * hv.y);
        }
        __syncthreads();

        // ---- Phase C: cand rh-GEMM partials -> psc
#pragma unroll
        for (int mh = 0; mh < 2; mh++) {
            const int mbase = mh * 4;
            const int mcnt  = mh ? 3 : 4;
            ull acc[4][2];
#pragma unroll
            for (int mm = 0; mm < 4; mm++)
                { acc[mm][0] = 0ull; acc[mm][1] = 0ull; }
#pragma unroll
            for (int mm = 0; mm < 4; mm++) {
                if (mm >= mcnt) break;
                const ulonglong2* p =
                    (const ulonglong2*)&S->srh[mbase + mm][cks * 8];
                ulonglong2 v0 = p[0], v1 = p[1];
#pragma unroll
                for (int c = 0; c < 2; c++) {
                    acc[mm][c] = ffma2(wc2[0][c], v0.x, acc[mm][c]);
                    acc[mm][c] = ffma2(wc2[1][c], v0.y, acc[mm][c]);
                    acc[mm][c] = ffma2(wc2[2][c], v1.x, acc[mm][c]);
                    acc[mm][c] = ffma2(wc2[3][c], v1.y, acc[mm][c]);
                }
            }
#pragma unroll
            for (int mm = 0; mm < 4; mm++) {
                if (mm >= mcnt) break;
                *(float2*)&S->psc[(cks * M_ + mbase + mm) * 64 + 2 * cng] =
                    make_float2(hadd2(acc[mm][0]), hadd2(acc[mm][1]));
            }
        }
        __syncthreads();

        // ---- Phase D: u-gate + cand finalize (tree adds) + update + output
        if (tid < M_ * 32) {
            int m = tid >> 5, n0 = (tid & 31) * 2;
            ull q0 = *(const ull*)&S->psg[(0 * M_ + m) * 128 + 64 + n0];
            ull q1 = *(const ull*)&S->psg[(1 * M_ + m) * 128 + 64 + n0];
            ull q2 = *(const ull*)&S->psg[(2 * M_ + m) * 128 + 64 + n0];
            ull q3 = *(const ull*)&S->psg[(3 * M_ + m) * 128 + 64 + n0];
            ull su_ = add2(add2(q0, q1), add2(q2, q3));
            su_ = add2(su_, *(const ull*)&S->sy1[buf][m][64 + n0]);
            float u0, u1; unpack2(su_, u0, u1);
            u0 = sigmoid_f(u0); u1 = sigmoid_f(u1);
            ull c0_ = *(const ull*)&S->psc[(0 * M_ + m) * 64 + n0];
            ull c1_ = *(const ull*)&S->psc[(1 * M_ + m) * 64 + n0];
            ull c2_ = *(const ull*)&S->psc[(2 * M_ + m) * 64 + n0];
            ull c3_ = *(const ull*)&S->psc[(3 * M_ + m) * 64 + n0];
            ull c4_ = *(const ull*)&S->psc[(4 * M_ + m) * 64 + n0];
            ull c5_ = *(const ull*)&S->psc[(5 * M_ + m) * 64 + n0];
            ull c6_ = *(const ull*)&S->psc[(6 * M_ + m) * 64 + n0];
            ull c7_ = *(const ull*)&S->psc[(7 * M_ + m) * 64 + n0];
            ull sc_ = add2(add2(add2(c0_, c1_), add2(c2_, c3_)),
                           add2(add2(c4_, c5_), add2(c6_, c7_)));
            sc_ = add2(sc_, *(const ull*)&S->sy2[buf][m][n0]);
            float c0, c1; unpack2(sc_, c0, c1);
            c0 = tanh_f(c0); c1 = tanh_f(c1);
            float2 hv = *(const float2*)&S->sh[m][n0];
            float a   = S->sa[buf][m];
            float uh0 = (1.0f - a) * u0;
            float uh1 = (1.0f - a) * u1;
            float hn0 = uh0 * hv.x + (1.0f - uh0) * c0;
            float hn1 = uh1 * hv.y + (1.0f - uh1) * c1;
            bool valid = (t < S->sl[m]);
            *(float2*)&S->sh[m][n0] =
                make_float2(valid ? hn0 : hv.x, valid ? hn1 : hv.y);
            int b = b0 + m;
            if (b < B_)
                *(float2*)&out[((size_t)b * T_ + t) * 64 + n0] =
                    make_float2(valid ? hn0 : 0.0f, valid ? hn1 : 0.0f);
        }
        asm volatile("cp.async.wait_group 1;");
        __syncthreads();
    }
    asm volatile("cp.async.wait_group 0;");
}

extern "C" void kernel_launch(void* const* d_in, const int* in_sizes, int n_in,
                              void* d_out, int out_size) {
    const float* x   = (const float*)d_in[0];
    const int*   sl  = (const int*)  d_in[1];
    const float* att = (const float*)d_in[2];
    const float* gk  = (const float*)d_in[3];
    const float* gb  = (const float*)d_in[4];
    const float* ck  = (const float*)d_in[5];
    const float* cb  = (const float*)d_in[6];
    float* out = (float*)d_out;

    cudaFuncSetAttribute(pre_kernel,
                         cudaFuncAttributeMaxDynamicSharedMemorySize, PSMEM_BYTES);
    pre_kernel<<<PGRID, PT, PSMEM_BYTES>>>(x, gk, gb, ck, cb);

    cudaFuncSetAttribute(augru_rec,
                         cudaFuncAttributeMaxDynamicSharedMemorySize, RSMEM_BYTES);
    augru_rec<<<NCTA_R, RTHREADS, RSMEM_BYTES>>>(sl, att, gk, ck, out);
}

// round 11
// speedup vs baseline: 2.1330x; 1.0066x over previous
#include <cuda_runtime.h>
#include <cstdint>

// AUGRU, B=2048, T=200, D=H=64. Two-kernel split.
//  K1 (pre): Y1 = x@Wgx + gb [BT,128], Y2 = x@Wcx + cb [BT,64].
//            W in smem; 8 rows/thread (weights amortized 8x), 64-row tiles,
//            2 CTAs/SM, depth-2 cp.async. FMA-rt-bound by construction.
//  K2 (rec): R8/R10 recurrence verbatim (measured 353us).

#define B_ 2048
#define T_ 200
#define D_ 64
#define H_ 64
#define BT_ (B_ * T_)

typedef unsigned long long ull;

__device__ float Y1g[BT_ * 128];
__device__ float Y2g[BT_ * 64];

__device__ __forceinline__ ull pack2(float lo, float hi) {
    ull r; asm("mov.b64 %0, {%1, %2};" : "=l"(r) : "f"(lo), "f"(hi)); return r;
}
__device__ __forceinline__ void unpack2(ull v, float& lo, float& hi) {
    asm("mov.b64 {%0, %1}, %2;" : "=f"(lo), "=f"(hi) : "l"(v));
}
__device__ __forceinline__ ull ffma2(ull a, ull b, ull c) {
    ull d; asm("fma.rn.f32x2 %0, %1, %2, %3;" : "=l"(d) : "l"(a), "l"(b), "l"(c)); return d;
}
__device__ __forceinline__ ull add2(ull a, ull b) {
    ull d; asm("add.rn.f32x2 %0, %1, %2;" : "=l"(d) : "l"(a), "l"(b)); return d;
}
__device__ __forceinline__ float hadd2(ull v) {
    float lo, hi; unpack2(v, lo, hi); return lo + hi;
}
__device__ __forceinline__ float sigmoid_f(float x) {
    return __fdividef(1.0f, 1.0f + __expf(-x));
}
__device__ __forceinline__ float tanh_f(float x) {
    float e = __expf(2.0f * x);
    return 1.0f - __fdividef(2.0f, e + 1.0f);
}
__device__ __forceinline__ void cpa16(void* s, const void* g) {
    uint32_t sa = (uint32_t)__cvta_generic_to_shared(s);
    asm volatile("cp.async.ca.shared.global [%0], [%1], 16;" :: "r"(sa), "l"(g));
}
__device__ __forceinline__ void cpa4(void* s, const void* g) {
    uint32_t sa = (uint32_t)__cvta_generic_to_shared(s);
    asm volatile("cp.async.ca.shared.global [%0], [%1], 4;" :: "r"(sa), "l"(g));
}

// ============================ K1: precompute ================================
#define PT 256
#define PGRID 296
#define PTILE_R 64
#define NT_P (BT_ / PTILE_R)   // 6400 exactly

struct PSmem {
    float w[64][192];            // combined [Wgx | Wcx], k-major
    float sx[3][PTILE_R][64];    // x tile, triple buffer
};
#define PSMEM_BYTES ((int)sizeof(PSmem))

__global__ __launch_bounds__(PT, 2)
void pre_kernel(const float* __restrict__ x,   // [BT, 64]
                const float* __restrict__ gk,  // [128,128]
                const float* __restrict__ gb,
                const float* __restrict__ ck,  // [128,64]
                const float* __restrict__ cb)
{
    extern __shared__ char praw[];
    PSmem* S = reinterpret_cast<PSmem*>(praw);
    const int tid = threadIdx.x;
    const int cg  = tid & 31;   // col-pairs: cols {2cg, 2cg+1} + 64j, j=0..2
    const int rg  = tid >> 5;   // rows rg*8 .. rg*8+7

    // Load combined W into smem (one-time)
    for (int idx = tid; idx < 64 * 48; idx += PT) {
        int k = idx / 48, c4 = idx % 48;
        float4 v;
        if (c4 < 32) v = ((const float4*)(gk + k * 128))[c4];
        else         v = ((const float4*)(ck + k * 64))[c4 - 32];
        ((float4*)&S->w[k][0])[c4] = v;
    }
    ull bias[3];
#pragma unroll
    for (int j = 0; j < 3; j++) {
        int c = 64 * j + 2 * cg;
        float lo = (c < 128) ? gb[c] : cb[c - 128];
        float hi = (c < 128) ? gb[c + 1] : cb[c + 1 - 128];
        bias[j] = pack2(lo, hi);
    }

    auto prefetch = [&](int tl, int bb) {
#pragma unroll
        for (int i = 0; i < 4; i++) {
            int idx = tid + i * PT;              // 1024 float4 per 64-row tile
            cpa16((char*)&S->sx[bb][0][0] + idx * 16,
                  x + (size_t)tl * PTILE_R * 64 + idx * 4);
        }
        asm volatile("cp.async.commit_group;");
    };

    // Prologue: two tiles in flight
    {
        int t0 = blockIdx.x;
        if (t0 < NT_P) prefetch(t0, 0);
        else asm volatile("cp.async.commit_group;");
        int t1 = t0 + PGRID;
        if (t1 < NT_P) prefetch(t1, 1);
        else asm volatile("cp.async.commit_group;");
    }

    int i = 0;
    for (int tile = blockIdx.x; tile < NT_P; tile += PGRID, i++) {
        asm volatile("cp.async.wait_group 1;");
        __syncthreads();                         // tile (and W first iter) visible
        {
            int pf = tile + 2 * PGRID;
            if (pf < NT_P) prefetch(pf, (i + 2) % 3);
            else asm volatile("cp.async.commit_group;");
        }
        const int buf = i % 3;

        ull acc[8][3];
#pragma unroll
        for (int r = 0; r < 8; r++)
#pragma unroll
            for (int j = 0; j < 3; j++) acc[r][j] = bias[j];

#pragma unroll 2
        for (int kk = 0; kk < 16; kk++) {
            // cache this kk's weight quads (4 k x 3 col-pairs) in regs:
            // amortized over 8 rows
            ull wk[4][3];
#pragma unroll
            for (int ks = 0; ks < 4; ks++) {
                const int k = 4 * kk + ks;
                wk[ks][0] = *(const ull*)&S->w[k][2 * cg];
                wk[ks][1] = *(const ull*)&S->w[k][64 + 2 * cg];
                wk[ks][2] = *(const ull*)&S->w[k][128 + 2 * cg];
            }
#pragma unroll
            for (int r = 0; r < 8; r++) {
                float4 v = *(const float4*)&S->sx[buf][rg * 8 + r][4 * kk];
                ull a0 = pack2(v.x, v.x), a1 = pack2(v.y, v.y);
                ull a2 = pack2(v.z, v.z), a3 = pack2(v.w, v.w);
#pragma unroll
                for (int j = 0; j < 3; j++) {
                    acc[r][j] = ffma2(wk[0][j], a0, acc[r][j]);
                    acc[r][j] = ffma2(wk[1][j], a1, acc[r][j]);
                    acc[r][j] = ffma2(wk[2][j], a2, acc[r][j]);
                    acc[r][j] = ffma2(wk[3][j], a3, acc[r][j]);
                }
            }
        }

#pragma unroll
        for (int r = 0; r < 8; r++) {
            size_t row = (size_t)tile * PTILE_R + rg * 8 + r;
            float lo, hi;
            unpack2(acc[r][0], lo, hi);
            *(float2*)&Y1g[row * 128 + 2 * cg]      = make_float2(lo, hi);
            unpack2(acc[r][1], lo, hi);
            *(float2*)&Y1g[row * 128 + 64 + 2 * cg] = make_float2(lo, hi);
            unpack2(acc[r][2], lo, hi);
            *(float2*)&Y2g[row * 64 + 2 * cg]       = make_float2(lo, hi);
        }
        __syncthreads();                         // reads done before buf reuse
    }
    asm volatile("cp.async.wait_group 0;");
}

// ============================ K2: recurrence (R10, measured 353us) ==========
#define M_ 7
#define RTHREADS 256
#define NCTA_R ((B_ + M_ - 1) / M_)   // 293

struct RSmem {
    float sy1[3][M_][128];
    float sy2[3][M_][64];
    float sh[M_][64];
    float srh[M_][64];
    float psg[4 * M_ * 128];
    float psc[8 * M_ * 64];
    float sa[3][8];
    int   sl[8];
};
#define RSMEM_BYTES ((int)sizeof(RSmem))

__global__ __launch_bounds__(RTHREADS, 2)
void augru_rec(const int*   __restrict__ slen_g,
               const float* __restrict__ att,
               const float* __restrict__ gk,
               const float* __restrict__ ck,
               float*       __restrict__ out)
{
    extern __shared__ char smem_raw[];
    RSmem* S = reinterpret_cast<RSmem*>(smem_raw);

    const int tid = threadIdx.x;
    const int b0  = blockIdx.x * M_;

    const int gng = tid & 63;
    const int gks = tid >> 6;
    const int cng = tid & 31;
    const int cks = tid >> 5;

    ull wg2[8][2];
#pragma unroll
    for (int kp = 0; kp < 8; kp++) {
        int k = 64 + gks * 16 + 2 * kp;
#pragma unroll
        for (int c = 0; c < 2; c++)
            wg2[kp][c] = pack2(gk[k * 128 + 2 * gng + c],
                               gk[(k + 1) * 128 + 2 * gng + c]);
    }
    ull wc2[4][2];
#pragma unroll
    for (int kp = 0; kp < 4; kp++) {
        int k = 64 + cks * 8 + 2 * kp;
#pragma unroll
        for (int c = 0; c < 2; c++)
            wc2[kp][c] = pack2(ck[k * 64 + 2 * cng + c],
                               ck[(k + 1) * 64 + 2 * cng + c]);
    }

    for (int idx = tid; idx < M_ * 64; idx += RTHREADS)
        (&S->sh[0][0])[idx] = 0.0f;
    if (tid < M_) {
        int b = b0 + tid; if (b >= B_) b = B_ - 1;
        S->sl[tid] = slen_g[b];
    }

    const int y1m = tid >> 5, y1q = tid & 31;
    const int y2m = tid >> 4, y2q = tid & 15;
    int by1 = b0 + y1m; if (by1 >= B_) by1 = B_ - 1;
    int by2 = b0 + y2m; if (by2 >= B_) by2 = B_ - 1;
    int ba  = b0 + tid; if (ba  >= B_) ba  = B_ - 1;

    auto do_prefetch = [&](int tt, int bb) {
        if (tid < 224)
            cpa16((char*)&S->sy1[bb][0][0] + tid * 16,
                  &Y1g[((size_t)by1 * T_ + tt) * 128 + y1q * 4]);
        if (tid < 112)
            cpa16((char*)&S->sy2[bb][0][0] + tid * 16,
                  &Y2g[((size_t)by2 * T_ + tt) * 64 + y2q * 4]);
        if (tid < M_)
            cpa4(&S->sa[bb][tid], &att[(size_t)ba * T_ + tt]);
        asm volatile("cp.async.commit_group;");
    };

    do_prefetch(0, 0);
    do_prefetch(1 < T_ ? 1 : 0, 1);
    asm volatile("cp.async.wait_group 1;");
    __syncthreads();

    for (int t = 0; t < T_; ++t) {
        const int buf = t % 3;
        {
            int tn = (t + 2 < T_) ? t + 2 : T_ - 1;
            do_prefetch(tn, (t + 2) % 3);
        }

        // ---- Phase A: gate h-GEMM partials -> psg
#pragma unroll
        for (int mh = 0; mh < 2; mh++) {
            const int mbase = mh * 4;
            const int mcnt  = mh ? 3 : 4;
            ull acc[4][2];
#pragma unroll
            for (int mm = 0; mm < 4; mm++)
                { acc[mm][0] = 0ull; acc[mm][1] = 0ull; }
#pragma unroll
            for (int mm = 0; mm < 4; mm++) {
                if (mm >= mcnt) break;
                const ulonglong2* p =
                    (const ulonglong2*)&S->sh[mbase + mm][gks * 16];
                ulonglong2 v0 = p[0], v1 = p[1], v2 = p[2], v3 = p[3];
#pragma unroll
                for (int c = 0; c < 2; c++) {
                    acc[mm][c] = ffma2(wg2[0][c], v0.x, acc[mm][c]);
                    acc[mm][c] = ffma2(wg2[1][c], v0.y, acc[mm][c]);
                    acc[mm][c] = ffma2(wg2[2][c], v1.x, acc[mm][c]);
                    acc[mm][c] = ffma2(wg2[3][c], v1.y, acc[mm][c]);
                    acc[mm][c] = ffma2(wg2[4][c], v2.x, acc[mm][c]);
                    acc[mm][c] = ffma2(wg2[5][c], v2.y, acc[mm][c]);
                    acc[mm][c] = ffma2(wg2[6][c], v3.x, acc[mm][c]);
                    acc[mm][c] = ffma2(wg2[7][c], v3.y, acc[mm][c]);
                }
            }
#pragma unroll
            for (int mm = 0; mm < 4; mm++) {
                if (mm >= mcnt) break;
                *(float2*)&S->psg[(gks * M_ + mbase + mm) * 128 + 2 * gng] =
                    make_float2(hadd2(acc[mm][0]), hadd2(acc[mm][1]));
            }
        }
        __syncthreads();

        // ---- Phase B: r-gate finalize (tree adds) -> srh
        if (tid < M_ * 32) {
            int m = tid >> 5, n0 = (tid & 31) * 2;
            ull p0 = *(const ull*)&S->psg[(0 * M_ + m) * 128 + n0];
            ull p1 = *(const ull*)&S->psg[(1 * M_ + m) * 128 + n0];
            ull p2 = *(const ull*)&S->psg[(2 * M_ + m) * 128 + n0];
            ull p3 = *(const ull*)&S->psg[(3 * M_ + m) * 128 + n0];
            ull s  = add2(add2(p0, p1), add2(p2, p3));
            s = add2(s, *(const ull*)&S->sy1[buf][m][n0]);
            float g0, g1; unpack2(s, g0, g1);
            g0 = sigmoid_f(g0); g1 = sigmoid_f(g1);
            float2 hv = *(const float2*)&S->sh[m][n0];
            *(float2*)&S->srh[m][n0] = make_float2(g0 * hv.x, g1 * hv.y);
        }
        __syncthreads();

        // ---- Phase C: cand rh-GEMM partials -> psc
#pragma unroll
        for (int mh = 0; mh < 2; mh++) {
            const int mbase = mh * 4;
            const int mcnt  = mh ? 3 : 4;
            ull acc[4][2];
#pragma unroll
            for (int mm = 0; mm < 4; mm++)
                { acc[mm][0] = 0ull; acc[mm][1] = 0ull; }
#pragma unroll
            for (int mm = 0; mm < 4; mm++) {
                if (mm >= mcnt) break;
                const ulonglong2* p =
                    (const ulonglong2*)&S->srh[mbase + mm][cks * 8];
                ulonglong2 v0 = p[0], v1 = p[1];
#pragma unroll
                for (int c = 0; c < 2; c++) {
                    acc[mm][c] = ffma2(wc2[0][c], v0.x, acc[mm][c]);
                    acc[mm][c] = ffma2(wc2[1][c], v0.y, acc[mm][c]);
                    acc[mm][c] = ffma2(wc2[2][c], v1.x, acc[mm][c]);
                    acc[mm][c] = ffma2(wc2[3][c], v1.y, acc[mm][c]);
                }
            }
#pragma unroll
            for (int mm = 0; mm < 4; mm++) {
                if (mm >= mcnt) break;
                *(float2*)&S->psc[(cks * M_ + mbase + mm) * 64 + 2 * cng] =
                    make_float2(hadd2(acc[mm][0]), hadd2(acc[mm][1]));
            }
        }
        __syncthreads();

        // ---- Phase D: u-gate + cand finalize (tree adds) + update + output
        if (tid < M_ * 32) {
            int m = tid >> 5, n0 = (tid & 31) * 2;
            ull q0 = *(const ull*)&S->psg[(0 * M_ + m) * 128 + 64 + n0];
            ull q1 = *(const ull*)&S->psg[(1 * M_ + m) * 128 + 64 + n0];
            ull q2 = *(const ull*)&S->psg[(2 * M_ + m) * 128 + 64 + n0];
            ull q3 = *(const ull*)&S->psg[(3 * M_ + m) * 128 + 64 + n0];
            ull su_ = add2(add2(q0, q1), add2(q2, q3));
            su_ = add2(su_, *(const ull*)&S->sy1[buf][m][64 + n0]);
            float u0, u1; unpack2(su_, u0, u1);
            u0 = sigmoid_f(u0); u1 = sigmoid_f(u1);
            ull c0_ = *(const ull*)&S->psc[(0 * M_ + m) * 64 + n0];
            ull c1_ = *(const ull*)&S->psc[(1 * M_ + m) * 64 + n0];
            ull c2_ = *(const ull*)&S->psc[(2 * M_ + m) * 64 + n0];
            ull c3_ = *(const ull*)&S->psc[(3 * M_ + m) * 64 + n0];
            ull c4_ = *(const ull*)&S->psc[(4 * M_ + m) * 64 + n0];
            ull c5_ = *(const ull*)&S->psc[(5 * M_ + m) * 64 + n0];
            ull c6_ = *(const ull*)&S->psc[(6 * M_ + m) * 64 + n0];
            ull c7_ = *(const ull*)&S->psc[(7 * M_ + m) * 64 + n0];
            ull sc_ = add2(add2(add2(c0_, c1_), add2(c2_, c3_)),
                           add2(add2(c4_, c5_), add2(c6_, c7_)));
            sc_ = add2(sc_, *(const ull*)&S->sy2[buf][m][n0]);
            float c0, c1; unpack2(sc_, c0, c1);
            c0 = tanh_f(c0); c1 = tanh_f(c1);
            float2 hv = *(const float2*)&S->sh[m][n0];
            float a   = S->sa[buf][m];
            float uh0 = (1.0f - a) * u0;
            float uh1 = (1.0f - a) * u1;
            float hn0 = uh0 * hv.x + (1.0f - uh0) * c0;
            float hn1 = uh1 * hv.y + (1.0f - uh1) * c1;
            bool valid = (t < S->sl[m]);
            *(float2*)&S->sh[m][n0] =
                make_float2(valid ? hn0 : hv.x, valid ? hn1 : hv.y);
            int b = b0 + m;
            if (b < B_)
                *(float2*)&out[((size_t)b * T_ + t) * 64 + n0] =
                    make_float2(valid ? hn0 : 0.0f, valid ? hn1 : 0.0f);
        }
        asm volatile("cp.async.wait_group 1;");
        __syncthreads();
    }
    asm volatile("cp.async.wait_group 0;");
}

extern "C" void kernel_launch(void* const* d_in, const int* in_sizes, int n_in,
                              void* d_out, int out_size) {
    const float* x   = (const float*)d_in[0];
    const int*   sl  = (const int*)  d_in[1];
    const float* att = (const float*)d_in[2];
    const float* gk  = (const float*)d_in[3];
    const float* gb  = (const float*)d_in[4];
    const float* ck  = (const float*)d_in[5];
    const float* cb  = (const float*)d_in[6];
    float* out = (float*)d_out;

    cudaFuncSetAttribute(pre_kernel,
                         cudaFuncAttributeMaxDynamicSharedMemorySize, PSMEM_BYTES);
    pre_kernel<<<PGRID, PT, PSMEM_BYTES>>>(x, gk, gb, ck, cb);

    cudaFuncSetAttribute(augru_rec,
                         cudaFuncAttributeMaxDynamicSharedMemorySize, RSMEM_BYTES);
    augru_rec<<<NCTA_R, RTHREADS, RSMEM_BYTES>>>(sl, att, gk, ck, out);
}

// round 12
// speedup vs baseline: 2.1737x; 1.0191x over previous
#include <cuda_runtime.h>
#include <cstdint>

// AUGRU, B=2048, T=200, D=H=64. Two-kernel split.
//  K1 (pre): Y1 = x@Wgx + gb [BT,128], Y2 = x@Wcx + cb [BT,64].
//            BARRIER-FREE warp-private streaming: each warp owns its own
//            8-row chunk stream with private triple-buffered cp.async.
//            Inner compute loop identical to R11 (proven).
//  K2 (rec): R11 recurrence verbatim (measured 352.7us).

#define B_ 2048
#define T_ 200
#define D_ 64
#define H_ 64
#define BT_ (B_ * T_)

typedef unsigned long long ull;

__device__ float Y1g[BT_ * 128];
__device__ float Y2g[BT_ * 64];

__device__ __forceinline__ ull pack2(float lo, float hi) {
    ull r; asm("mov.b64 %0, {%1, %2};" : "=l"(r) : "f"(lo), "f"(hi)); return r;
}
__device__ __forceinline__ void unpack2(ull v, float& lo, float& hi) {
    asm("mov.b64 {%0, %1}, %2;" : "=f"(lo), "=f"(hi) : "l"(v));
}
__device__ __forceinline__ ull ffma2(ull a, ull b, ull c) {
    ull d; asm("fma.rn.f32x2 %0, %1, %2, %3;" : "=l"(d) : "l"(a), "l"(b), "l"(c)); return d;
}
__device__ __forceinline__ ull add2(ull a, ull b) {
    ull d; asm("add.rn.f32x2 %0, %1, %2;" : "=l"(d) : "l"(a), "l"(b)); return d;
}
__device__ __forceinline__ float hadd2(ull v) {
    float lo, hi; unpack2(v, lo, hi); return lo + hi;
}
__device__ __forceinline__ float sigmoid_f(float x) {
    return __fdividef(1.0f, 1.0f + __expf(-x));
}
__device__ __forceinline__ float tanh_f(float x) {
    float e = __expf(2.0f * x);
    return 1.0f - __fdividef(2.0f, e + 1.0f);
}
__device__ __forceinline__ void cpa16(void* s, const void* g) {
    uint32_t sa = (uint32_t)__cvta_generic_to_shared(s);
    asm volatile("cp.async.ca.shared.global [%0], [%1], 16;" :: "r"(sa), "l"(g));
}
__device__ __forceinline__ void cpa4(void* s, const void* g) {
    uint32_t sa = (uint32_t)__cvta_generic_to_shared(s);
    asm volatile("cp.async.ca.shared.global [%0], [%1], 4;" :: "r"(sa), "l"(g));
}

// ============================ K1: precompute ================================
#define PT 256
#define PGRID 296
#define NCH (BT_ / 8)            // 51200 8-row chunks

struct PSmem {
    float w[64][192];            // combined [Wgx | Wcx], k-major (shared, RO)
    float sx[8][3][8][64];       // per-warp private triple-buffered x chunks
};
#define PSMEM_BYTES ((int)sizeof(PSmem))

__global__ __launch_bounds__(PT, 2)
void pre_kernel(const float* __restrict__ x,   // [BT, 64]
                const float* __restrict__ gk,  // [128,128]
                const float* __restrict__ gb,
                const float* __restrict__ ck,  // [128,64]
                const float* __restrict__ cb)
{
    extern __shared__ char praw[];
    PSmem* S = reinterpret_cast<PSmem*>(praw);
    const int tid  = threadIdx.x;
    const int lane = tid & 31;
    const int wid  = tid >> 5;
    const int cg   = lane;       // col-pairs: cols {2cg, 2cg+1} + 64j, j=0..2

    // Load combined W into smem (one-time, then read-only)
    for (int idx = tid; idx < 64 * 48; idx += PT) {
        int k = idx / 48, c4 = idx % 48;
        float4 v;
        if (c4 < 32) v = ((const float4*)(gk + k * 128))[c4];
        else         v = ((const float4*)(ck + k * 64))[c4 - 32];
        ((float4*)&S->w[k][0])[c4] = v;
    }
    ull bias[3];
#pragma unroll
    for (int j = 0; j < 3; j++) {
        int c = 64 * j + 2 * cg;
        float lo = (c < 128) ? gb[c] : cb[c - 128];
        float hi = (c < 128) ? gb[c + 1] : cb[c + 1 - 128];
        bias[j] = pack2(lo, hi);
    }
    __syncthreads();             // W visible to all warps; ONLY CTA barrier

    const int stride = PGRID * 8;
    const int c0     = blockIdx.x * 8 + wid;

    // per-warp private fetch: chunk ch -> buffer bb (2 KB, 4 cp.async/lane)
    auto fetchc = [&](int ch, int bb) {
        if (ch > NCH - 1) ch = NCH - 1;          // clamp (redundant, harmless)
        const char* src = (const char*)(x + (size_t)ch * 8 * 64);
        char* dst = (char*)&S->sx[wid][bb][0][0];
#pragma unroll
        for (int j = 0; j < 4; j++)
            cpa16(dst + (lane + j * 32) * 16, src + (lane + j * 32) * 16);
        asm volatile("cp.async.commit_group;");
    };

    fetchc(c0, 0);
    fetchc(c0 + stride, 1);

    int i = 0;
    for (int ch = c0; ch < NCH; ch += stride, i++) {
        asm volatile("cp.async.wait_group 1;");
        __syncwarp();                            // cross-lane visibility
        fetchc(ch + 2 * stride, (i + 2) % 3);
        const int buf = i % 3;

        ull acc[8][3];
#pragma unroll
        for (int r = 0; r < 8; r++)
#pragma unroll
            for (int j = 0; j < 3; j++) acc[r][j] = bias[j];

#pragma unroll 2
        for (int kk = 0; kk < 16; kk++) {
            ull wk[4][3];
#pragma unroll
            for (int ks = 0; ks < 4; ks++) {
                const int k = 4 * kk + ks;
                wk[ks][0] = *(const ull*)&S->w[k][2 * cg];
                wk[ks][1] = *(const ull*)&S->w[k][64 + 2 * cg];
                wk[ks][2] = *(const ull*)&S->w[k][128 + 2 * cg];
            }
#pragma unroll
            for (int r = 0; r < 8; r++) {
                float4 v = *(const float4*)&S->sx[wid][buf][r][4 * kk];
                ull a0 = pack2(v.x, v.x), a1 = pack2(v.y, v.y);
                ull a2 = pack2(v.z, v.z), a3 = pack2(v.w, v.w);
#pragma unroll
                for (int j = 0; j < 3; j++) {
                    acc[r][j] = ffma2(wk[0][j], a0, acc[r][j]);
                    acc[r][j] = ffma2(wk[1][j], a1, acc[r][j]);
                    acc[r][j] = ffma2(wk[2][j], a2, acc[r][j]);
                    acc[r][j] = ffma2(wk[3][j], a3, acc[r][j]);
                }
            }
        }

#pragma unroll
        for (int r = 0; r < 8; r++) {
            size_t row = (size_t)ch * 8 + r;
            float lo, hi;
            unpack2(acc[r][0], lo, hi);
            *(float2*)&Y1g[row * 128 + 2 * cg]      = make_float2(lo, hi);
            unpack2(acc[r][1], lo, hi);
            *(float2*)&Y1g[row * 128 + 64 + 2 * cg] = make_float2(lo, hi);
            unpack2(acc[r][2], lo, hi);
            *(float2*)&Y2g[row * 64 + 2 * cg]       = make_float2(lo, hi);
        }
        // no barrier: buffer (i+2)%3 overwritten above was consumed at iter i-1
        // by THIS warp (program order) — no cross-warp sharing of sx.
    }
    asm volatile("cp.async.wait_group 0;");
}

// ============================ K2: recurrence (R11, measured 352.7us) ========
#define M_ 7
#define RTHREADS 256
#define NCTA_R ((B_ + M_ - 1) / M_)   // 293

struct RSmem {
    float sy1[3][M_][128];
    float sy2[3][M_][64];
    float sh[M_][64];
    float srh[M_][64];
    float psg[4 * M_ * 128];
    float psc[8 * M_ * 64];
    float sa[3][8];
    int   sl[8];
};
#define RSMEM_BYTES ((int)sizeof(RSmem))

__global__ __launch_bounds__(RTHREADS, 2)
void augru_rec(const int*   __restrict__ slen_g,
               const float* __restrict__ att,
               const float* __restrict__ gk,
               const float* __restrict__ ck,
               float*       __restrict__ out)
{
    extern __shared__ char smem_raw[];
    RSmem* S = reinterpret_cast<RSmem*>(smem_raw);

    const int tid = threadIdx.x;
    const int b0  = blockIdx.x * M_;

    const int gng = tid & 63;
    const int gks = tid >> 6;
    const int cng = tid & 31;
    const int cks = tid >> 5;

    ull wg2[8][2];
#pragma unroll
    for (int kp = 0; kp < 8; kp++) {
        int k = 64 + gks * 16 + 2 * kp;
#pragma unroll
        for (int c = 0; c < 2; c++)
            wg2[kp][c] = pack2(gk[k * 128 + 2 * gng + c],
                               gk[(k + 1) * 128 + 2 * gng + c]);
    }
    ull wc2[4][2];
#pragma unroll
    for (int kp = 0; kp < 4; kp++) {
        int k = 64 + cks * 8 + 2 * kp;
#pragma unroll
        for (int c = 0; c < 2; c++)
            wc2[kp][c] = pack2(ck[k * 64 + 2 * cng + c],
                               ck[(k + 1) * 64 + 2 * cng + c]);
    }

    for (int idx = tid; idx < M_ * 64; idx += RTHREADS)
        (&S->sh[0][0])[idx] = 0.0f;
    if (tid < M_) {
        int b = b0 + tid; if (b >= B_) b = B_ - 1;
        S->sl[tid] = slen_g[b];
    }

    const int y1m = tid >> 5, y1q = tid & 31;
    const int y2m = tid >> 4, y2q = tid & 15;
    int by1 = b0 + y1m; if (by1 >= B_) by1 = B_ - 1;
    int by2 = b0 + y2m; if (by2 >= B_) by2 = B_ - 1;
    int ba  = b0 + tid; if (ba  >= B_) ba  = B_ - 1;

    auto do_prefetch = [&](int tt, int bb) {
        if (tid < 224)
            cpa16((char*)&S->sy1[bb][0][0] + tid * 16,
                  &Y1g[((size_t)by1 * T_ + tt) * 128 + y1q * 4]);
        if (tid < 112)
            cpa16((char*)&S->sy2[bb][0][0] + tid * 16,
                  &Y2g[((size_t)by2 * T_ + tt) * 64 + y2q * 4]);
        if (tid < M_)
            cpa4(&S->sa[bb][tid], &att[(size_t)ba * T_ + tt]);
        asm volatile("cp.async.commit_group;");
    };

    do_prefetch(0, 0);
    do_prefetch(1 < T_ ? 1 : 0, 1);
    asm volatile("cp.async.wait_group 1;");
    __syncthreads();

    for (int t = 0; t < T_; ++t) {
        const int buf = t % 3;
        {
            int tn = (t + 2 < T_) ? t + 2 : T_ - 1;
            do_prefetch(tn, (t + 2) % 3);
        }

        // ---- Phase A: gate h-GEMM partials -> psg
#pragma unroll
        for (int mh = 0; mh < 2; mh++) {
            const int mbase = mh * 4;
            const int mcnt  = mh ? 3 : 4;
            ull acc[4][2];
#pragma unroll
            for (int mm = 0; mm < 4; mm++)
                { acc[mm][0] = 0ull; acc[mm][1] = 0ull; }
#pragma unroll
            for (int mm = 0; mm < 4; mm++) {
                if (mm >= mcnt) break;
                const ulonglong2* p =
                    (const ulonglong2*)&S->sh[mbase + mm][gks * 16];
                ulonglong2 v0 = p[0], v1 = p[1], v2 = p[2], v3 = p[3];
#pragma unroll
                for (int c = 0; c < 2; c++) {
                    acc[mm][c] = ffma2(wg2[0][c], v0.x, acc[mm][c]);
                    acc[mm][c] = ffma2(wg2[1][c], v0.y, acc[mm][c]);
                    acc[mm][c] = ffma2(wg2[2][c], v1.x, acc[mm][c]);
                    acc[mm][c] = ffma2(wg2[3][c], v1.y, acc[mm][c]);
                    acc[mm][c] = ffma2(wg2[4][c], v2.x, acc[mm][c]);
                    acc[mm][c] = ffma2(wg2[5][c], v2.y, acc[mm][c]);
                    acc[mm][c] = ffma2(wg2[6][c], v3.x, acc[mm][c]);
                    acc[mm][c] = ffma2(wg2[7][c], v3.y, acc[mm][c]);
                }
            }
#pragma unroll
            for (int mm = 0; mm < 4; mm++) {
                if (mm >= mcnt) break;
                *(float2*)&S->psg[(gks * M_ + mbase + mm) * 128 + 2 * gng] =
                    make_float2(hadd2(acc[mm][0]), hadd2(acc[mm][1]));
            }
        }
        __syncthreads();

        // ---- Phase B: r-gate finalize (tree adds) -> srh
        if (tid < M_ * 32) {
            int m = tid >> 5, n0 = (tid & 31) * 2;
            ull p0 = *(const ull*)&S->psg[(0 * M_ + m) * 128 + n0];
            ull p1 = *(const ull*)&S->psg[(1 * M_ + m) * 128 + n0];
            ull p2 = *(const ull*)&S->psg[(2 * M_ + m) * 128 + n0];
            ull p3 = *(const ull*)&S->psg[(3 * M_ + m) * 128 + n0];
            ull s  = add2(add2(p0, p1), add2(p2, p3));
            s = add2(s, *(const ull*)&S->sy1[buf][m][n0]);
            float g0, g1; unpack2(s, g0, g1);
            g0 = sigmoid_f(g0); g1 = sigmoid_f(g1);
            float2 hv = *(const float2*)&S->sh[m][n0];
            *(float2*)&S->srh[m][n0] = make_float2(g0 * hv.x, g1 * hv.y);
        }
        __syncthreads();

        // ---- Phase C: cand rh-GEMM partials -> psc
#pragma unroll
        for (int mh = 0; mh < 2; mh++) {
            const int mbase = mh * 4;
            const int mcnt  = mh ? 3 : 4;
            ull acc[4][2];
#pragma unroll
            for (int mm = 0; mm < 4; mm++)
                { acc[mm][0] = 0ull; acc[mm][1] = 0ull; }
#pragma unroll
            for (int mm = 0; mm < 4; mm++) {
                if (mm >= mcnt) break;
                const ulonglong2* p =
                    (const ulonglong2*)&S->srh[mbase + mm][cks * 8];
                ulonglong2 v0 = p[0], v1 = p[1];
#pragma unroll
                for (int c = 0; c < 2; c++) {
                    acc[mm][c] = ffma2(wc2[0][c], v0.x, acc[mm][c]);
                    acc[mm][c] = ffma2(wc2[1][c], v0.y, acc[mm][c]);
                    acc[mm][c] = ffma2(wc2[2][c], v1.x, acc[mm][c]);
                    acc[mm][c] = ffma2(wc2[3][c], v1.y, acc[mm][c]);
                }
            }
#pragma unroll
            for (int mm = 0; mm < 4; mm++) {
                if (mm >= mcnt) break;
                *(float2*)&S->psc[(cks * M_ + mbase + mm) * 64 + 2 * cng] =
                    make_float2(hadd2(acc[mm][0]), hadd2(acc[mm][1]));
            }
        }
        __syncthreads();

        // ---- Phase D: u-gate + cand finalize (tree adds) + update + output
        if (tid < M_ * 32) {
            int m = tid >> 5, n0 = (tid & 31) * 2;
            ull q0 = *(const ull*)&S->psg[(0 * M_ + m) * 128 + 64 + n0];
            ull q1 = *(const ull*)&S->psg[(1 * M_ + m) * 128 + 64 + n0];
            ull q2 = *(const ull*)&S->psg[(2 * M_ + m) * 128 + 64 + n0];
            ull q3 = *(const ull*)&S->psg[(3 * M_ + m) * 128 + 64 + n0];
            ull su_ = add2(add2(q0, q1), add2(q2, q3));
            su_ = add2(su_, *(const ull*)&S->sy1[buf][m][64 + n0]);
            float u0, u1; unpack2(su_, u0, u1);
            u0 = sigmoid_f(u0); u1 = sigmoid_f(u1);
            ull c0_ = *(const ull*)&S->psc[(0 * M_ + m) * 64 + n0];
            ull c1_ = *(const ull*)&S->psc[(1 * M_ + m) * 64 + n0];
            ull c2_ = *(const ull*)&S->psc[(2 * M_ + m) * 64 + n0];
            ull c3_ = *(const ull*)&S->psc[(3 * M_ + m) * 64 + n0];
            ull c4_ = *(const ull*)&S->psc[(4 * M_ + m) * 64 + n0];
            ull c5_ = *(const ull*)&S->psc[(5 * M_ + m) * 64 + n0];
            ull c6_ = *(const ull*)&S->psc[(6 * M_ + m) * 64 + n0];
            ull c7_ = *(const ull*)&S->psc[(7 * M_ + m) * 64 + n0];
            ull sc_ = add2(add2(add2(c0_, c1_), add2(c2_, c3_)),
                           add2(add2(c4_, c5_), add2(c6_, c7_)));
            sc_ = add2(sc_, *(const ull*)&S->sy2[buf][m][n0]);
            float c0, c1; unpack2(sc_, c0, c1);
            c0 = tanh_f(c0); c1 = tanh_f(c1);
            float2 hv = *(const float2*)&S->sh[m][n0];
            float a   = S->sa[buf][m];
            float uh0 = (1.0f - a) * u0;
            float uh1 = (1.0f - a) * u1;
            float hn0 = uh0 * hv.x + (1.0f - uh0) * c0;
            float hn1 = uh1 * hv.y + (1.0f - uh1) * c1;
            bool valid = (t < S->sl[m]);
            *(float2*)&S->sh[m][n0] =
                make_float2(valid ? hn0 : hv.x, valid ? hn1 : hv.y);
            int b = b0 + m;
            if (b < B_)
                *(float2*)&out[((size_t)b * T_ + t) * 64 + n0] =
                    make_float2(valid ? hn0 : 0.0f, valid ? hn1 : 0.0f);
        }
        asm volatile("cp.async.wait_group 1;");
        __syncthreads();
    }
    asm volatile("cp.async.wait_group 0;");
}

extern "C" void kernel_launch(void* const* d_in, const int* in_sizes, int n_in,
                              void* d_out, int out_size) {
    const float* x   = (const float*)d_in[0];
    const int*   sl  = (const int*)  d_in[1];
    const float* att = (const float*)d_in[2];
    const float* gk  = (const float*)d_in[3];
    const float* gb  = (const float*)d_in[4];
    const float* ck  = (const float*)d_in[5];
    const float* cb  = (const float*)d_in[6];
    float* out = (float*)d_out;

    cudaFuncSetAttribute(pre_kernel,
                         cudaFuncAttributeMaxDynamicSharedMemorySize, PSMEM_BYTES);
    pre_kernel<<<PGRID, PT, PSMEM_BYTES>>>(x, gk, gb, ck, cb);

    cudaFuncSetAttribute(augru_rec,
                         cudaFuncAttributeMaxDynamicSharedMemorySize, RSMEM_BYTES);
    augru_rec<<<NCTA_R, RTHREADS, RSMEM_BYTES>>>(sl, att, gk, ck, out);
}

// round 14
// speedup vs baseline: 2.6546x; 1.2212x over previous
#include <cuda_runtime.h>
#include <cuda_bf16.h>
#include <cstdint>

// AUGRU, B=2048, T=200, D=H=64. Two-kernel split.
//  K1 (pre): Y = x@[Wgx|Wcx]+bias on TENSOR pipe via portable
//            mma.sync.m16n8k16 bf16 (3-term split-bf16, fp32 accum).
//            W fragments register-resident; x via swizzled smem + ldmatrix.
//  K2 (rec): R12 recurrence verbatim (353us, seven rounds stable).

#define B_ 2048
#define T_ 200
#define D_ 64
#define H_ 64
#define BT_ (B_ * T_)

typedef unsigned long long ull;

__device__ float Y1g[BT_ * 128];
__device__ float Y2g[BT_ * 64];

__device__ __forceinline__ ull pack2(float lo, float hi) {
    ull r; asm("mov.b64 %0, {%1, %2};" : "=l"(r) : "f"(lo), "f"(hi)); return r;
}
__device__ __forceinline__ void unpack2(ull v, float& lo, float& hi) {
    asm("mov.b64 {%0, %1}, %2;" : "=f"(lo), "=f"(hi) : "l"(v));
}
__device__ __forceinline__ ull ffma2(ull a, ull b, ull c) {
    ull d; asm("fma.rn.f32x2 %0, %1, %2, %3;" : "=l"(d) : "l"(a), "l"(b), "l"(c)); return d;
}
__device__ __forceinline__ ull add2(ull a, ull b) {
    ull d; asm("add.rn.f32x2 %0, %1, %2;" : "=l"(d) : "l"(a), "l"(b)); return d;
}
__device__ __forceinline__ float hadd2(ull v) {
    float lo, hi; unpack2(v, lo, hi); return lo + hi;
}
__device__ __forceinline__ float sigmoid_f(float x) {
    return __fdividef(1.0f, 1.0f + __expf(-x));
}
__device__ __forceinline__ float tanh_f(float x) {
    float e = __expf(2.0f * x);
    return 1.0f - __fdividef(2.0f, e + 1.0f);
}
__device__ __forceinline__ void cpa16(void* s, const void* g) {
    uint32_t sa = (uint32_t)__cvta_generic_to_shared(s);
    asm volatile("cp.async.ca.shared.global [%0], [%1], 16;" :: "r"(sa), "l"(g));
}
__device__ __forceinline__ void cpa4(void* s, const void* g) {
    uint32_t sa = (uint32_t)__cvta_generic_to_shared(s);
    asm volatile("cp.async.ca.shared.global [%0], [%1], 4;" :: "r"(sa), "l"(g));
}

// ---------------- portable tensor helpers ----------------
__device__ __forceinline__ uint32_t smem_u32(const void* p) {
    uint32_t a;
    asm("{ .reg .u64 t; cvta.to.shared.u64 t, %1; cvt.u32.u64 %0, t; }"
        : "=r"(a) : "l"(p));
    return a;
}
__device__ __forceinline__ uint32_t bfpack(float a, float b) {
    __nv_bfloat162 t = __floats2bfloat162_rn(a, b);   // x=a (low), y=b (high)
    uint32_t r; memcpy(&r, &t, 4); return r;
}
__device__ __forceinline__ void bfsplit(float v, __nv_bfloat16& hi, float& rem) {
    hi = __float2bfloat16(v);
    rem = v - __bfloat162float(hi);
}
__device__ __forceinline__ void mma16816(float& c0, float& c1, float& c2, float& c3,
                                         uint32_t a0, uint32_t a1, uint32_t a2, uint32_t a3,
                                         uint32_t b0, uint32_t b1) {
    asm volatile(
        "mma.sync.aligned.m16n8k16.row.col.f32.bf16.bf16.f32 "
        "{%0,%1,%2,%3}, {%4,%5,%6,%7}, {%8,%9}, {%0,%1,%2,%3};"
        : "+f"(c0), "+f"(c1), "+f"(c2), "+f"(c3)
        : "r"(a0), "r"(a1), "r"(a2), "r"(a3), "r"(b0), "r"(b1));
}
__device__ __forceinline__ void ldmx4(uint32_t& r0, uint32_t& r1,
                                      uint32_t& r2, uint32_t& r3, uint32_t addr) {
    asm volatile("ldmatrix.sync.aligned.m8n8.x4.shared.b16 {%0,%1,%2,%3}, [%4];"
                 : "=r"(r0), "=r"(r1), "=r"(r2), "=r"(r3) : "r"(addr));
}

// ============================ K1: precompute (mma.sync) =====================
#define PT 256
#define PGRID 296
#define NTILE (BT_ / 16)   // 25600 16-row tiles

__global__ __launch_bounds__(PT, 2)
void pre_kernel(const float* __restrict__ x,   // [BT, 64]
                const float* __restrict__ gk,  // [128,128]
                const float* __restrict__ gb,
                const float* __restrict__ ck,  // [128,64]
                const float* __restrict__ cb)
{
    // A tiles: 16 rows x 64 cols bf16 = 2 KB each (hi, lo), swizzled
    __shared__ __align__(128) char sA[4096];
    const uint32_t sAhi = smem_u32(sA);
    const uint32_t sAlo = sAhi + 2048;

    const int tid  = threadIdx.x;
    const int wid  = tid >> 5;     // 0..7 -> 24-col slice
    const int lane = tid & 31;
    const int lq   = lane & 3;     // l%4
    const int ln   = lane >> 2;    // l/4

    // ---- register-resident W fragments (B operand), 3-term split ----
    // block b: cols w*24 + b*8 + ln ; k0 = ks*16 + 2*lq
    uint32_t Bh[3][4][2], Bl[3][4][2];
    float2 bias[3];
#pragma unroll
    for (int b = 0; b < 3; b++) {
        const int n = wid * 24 + b * 8 + ln;
        const int cb0 = wid * 24 + b * 8 + 2 * lq;
        if (cb0 < 128) bias[b] = make_float2(gb[cb0], gb[cb0 + 1]);
        else           bias[b] = make_float2(cb[cb0 - 128], cb[cb0 - 127]);
#pragma unroll
        for (int ks = 0; ks < 4; ks++) {
            const int k0 = ks * 16 + 2 * lq;
            float w[4];
#pragma unroll
            for (int j = 0; j < 4; j++) {
                const int k = k0 + (j >> 1) * 8 + (j & 1);
                w[j] = (n < 128) ? gk[k * 128 + n] : ck[k * 64 + (n - 128)];
            }
            __nv_bfloat16 h; float r_;
            float hi[4], lo[4];
#pragma unroll
            for (int j = 0; j < 4; j++) {
                bfsplit(w[j], h, r_);
                hi[j] = __bfloat162float(h);
                lo[j] = r_;
            }
            Bh[b][ks][0] = bfpack(hi[0], hi[1]);
            Bh[b][ks][1] = bfpack(hi[2], hi[3]);
            Bl[b][ks][0] = bfpack(lo[0], lo[1]);
            Bl[b][ks][1] = bfpack(lo[2], lo[3]);
        }
    }

    // x element mapping: thread -> (row r, 4 k's at kq)
    const int r  = tid >> 4;        // 0..15
    const int kq = (tid & 15) * 4;  // 0,4,...,60
    const uint32_t chunk = (uint32_t)(kq >> 3);
    const uint32_t aoff  = (uint32_t)r * 128 +
                           (((chunk ^ (uint32_t)(r & 7)) & 7) << 4) +
                           (uint32_t)(kq & 7) * 2;

    // prefetch first tile
    float4 pf = make_float4(0.f, 0.f, 0.f, 0.f);
    {
        int t0 = blockIdx.x;
        if (t0 < NTILE)
            pf = *(const float4*)(x + ((size_t)t0 * 16 + r) * 64 + kq);
    }

    for (int tile = blockIdx.x; tile < NTILE; tile += PGRID) {
        // convert prefetched x -> smem hi/lo (swizzled)
        {
            __nv_bfloat16 h; float rem;
            float hx, hy, hz, hw, lx, ly, lz, lw;
            bfsplit(pf.x, h, rem); hx = __bfloat162float(h); lx = rem;
            bfsplit(pf.y, h, rem); hy = __bfloat162float(h); ly = rem;
            bfsplit(pf.z, h, rem); hz = __bfloat162float(h); lz = rem;
            bfsplit(pf.w, h, rem); hw = __bfloat162float(h); lw = rem;
            *(uint32_t*)(sA + (sAhi - smem_u32(sA)) + aoff)     = bfpack(hx, hy);
            *(uint32_t*)(sA + (sAhi - smem_u32(sA)) + aoff + 4) = bfpack(hz, hw);
            *(uint32_t*)(sA + 2048 + aoff)     = bfpack(lx, ly);
            *(uint32_t*)(sA + 2048 + aoff + 4) = bfpack(lz, lw);
        }
        __syncthreads();

        // prefetch next tile (overlaps MMA)
        {
            int nt = tile + PGRID;
            if (nt < NTILE)
                pf = *(const float4*)(x + ((size_t)nt * 16 + r) * 64 + kq);
        }

        // accumulators init with bias
        float c[3][4];
#pragma unroll
        for (int b = 0; b < 3; b++) {
            c[b][0] = bias[b].x; c[b][1] = bias[b].y;
            c[b][2] = bias[b].x; c[b][3] = bias[b].y;
        }

        // ldmatrix lane address pieces (tile order a0..a3)
        const int tI = lane >> 3;                   // 0..3
        const int rr = ((tI & 1) << 3) + (lane & 7);
        const int cI = tI >> 1;                     // chunk offset within kstep

#pragma unroll
        for (int ks = 0; ks < 4; ks++) {
            const uint32_t ch  = (uint32_t)(2 * ks + cI);
            const uint32_t la  = (uint32_t)rr * 128 +
                                 (((ch ^ (uint32_t)(rr & 7)) & 7) << 4);
            uint32_t ah0, ah1, ah2, ah3, al0, al1, al2, al3;
            ldmx4(ah0, ah1, ah2, ah3, sAhi + la);
            ldmx4(al0, al1, al2, al3, sAlo + la);
#pragma unroll
            for (int b = 0; b < 3; b++) {
                mma16816(c[b][0], c[b][1], c[b][2], c[b][3],
                         ah0, ah1, ah2, ah3, Bh[b][ks][0], Bh[b][ks][1]);
                mma16816(c[b][0], c[b][1], c[b][2], c[b][3],
                         ah0, ah1, ah2, ah3, Bl[b][ks][0], Bl[b][ks][1]);
                mma16816(c[b][0], c[b][1], c[b][2], c[b][3],
                         al0, al1, al2, al3, Bh[b][ks][0], Bh[b][ks][1]);
            }
        }

        // epilogue: C -> global (rows ln, ln+8; cols col0+2lq)
        {
            const size_t row0 = (size_t)tile * 16 + ln;
#pragma unroll
            for (int b = 0; b < 3; b++) {
                const int col = wid * 24 + b * 8 + 2 * lq;
                if (col < 128) {
                    *(float2*)&Y1g[row0 * 128 + col]       = make_float2(c[b][0], c[b][1]);
                    *(float2*)&Y1g[(row0 + 8) * 128 + col] = make_float2(c[b][2], c[b][3]);
                } else {
                    *(float2*)&Y2g[row0 * 64 + col - 128]       = make_float2(c[b][0], c[b][1]);
                    *(float2*)&Y2g[(row0 + 8) * 64 + col - 128] = make_float2(c[b][2], c[b][3]);
                }
            }
        }
        __syncthreads();   // smem A free for next store pass
    }
}

// ============================ K2: recurrence (R12, 353us) ===================
#define M_ 7
#define RTHREADS 256
#define NCTA_R ((B_ + M_ - 1) / M_)   // 293

struct RSmem {
    float sy1[3][M_][128];
    float sy2[3][M_][64];
    float sh[M_][64];
    float srh[M_][64];
    float psg[4 * M_ * 128];
    float psc[8 * M_ * 64];
    float sa[3][8];
    int   sl[8];
};
#define RSMEM_BYTES ((int)sizeof(RSmem))

__global__ __launch_bounds__(RTHREADS, 2)
void augru_rec(const int*   __restrict__ slen_g,
               const float* __restrict__ att,
               const float* __restrict__ gk,
               const float* __restrict__ ck,
               float*       __restrict__ out)
{
    extern __shared__ char smem_raw[];
    RSmem* S = reinterpret_cast<RSmem*>(smem_raw);

    const int tid = threadIdx.x;
    const int b0  = blockIdx.x * M_;

    const int gng = tid & 63;
    const int gks = tid >> 6;
    const int cng = tid & 31;
    const int cks = tid >> 5;

    ull wg2[8][2];
#pragma unroll
    for (int kp = 0; kp < 8; kp++) {
        int k = 64 + gks * 16 + 2 * kp;
#pragma unroll
        for (int c = 0; c < 2; c++)
            wg2[kp][c] = pack2(gk[k * 128 + 2 * gng + c],
                               gk[(k + 1) * 128 + 2 * gng + c]);
    }
    ull wc2[4][2];
#pragma unroll
    for (int kp = 0; kp < 4; kp++) {
        int k = 64 + cks * 8 + 2 * kp;
#pragma unroll
        for (int c = 0; c < 2; c++)
            wc2[kp][c] = pack2(ck[k * 64 + 2 * cng + c],
                               ck[(k + 1) * 64 + 2 * cng + c]);
    }

    for (int idx = tid; idx < M_ * 64; idx += RTHREADS)
        (&S->sh[0][0])[idx] = 0.0f;
    if (tid < M_) {
        int b = b0 + tid; if (b >= B_) b = B_ - 1;
        S->sl[tid] = slen_g[b];
    }

    const int y1m = tid >> 5, y1q = tid & 31;
    const int y2m = tid >> 4, y2q = tid & 15;
    int by1 = b0 + y1m; if (by1 >= B_) by1 = B_ - 1;
    int by2 = b0 + y2m; if (by2 >= B_) by2 = B_ - 1;
    int ba  = b0 + tid; if (ba  >= B_) ba  = B_ - 1;

    auto do_prefetch = [&](int tt, int bb) {
        if (tid < 224)
            cpa16((char*)&S->sy1[bb][0][0] + tid * 16,
                  &Y1g[((size_t)by1 * T_ + tt) * 128 + y1q * 4]);
        if (tid < 112)
            cpa16((char*)&S->sy2[bb][0][0] + tid * 16,
                  &Y2g[((size_t)by2 * T_ + tt) * 64 + y2q * 4]);
        if (tid < M_)
            cpa4(&S->sa[bb][tid], &att[(size_t)ba * T_ + tt]);
        asm volatile("cp.async.commit_group;");
    };

    do_prefetch(0, 0);
    do_prefetch(1 < T_ ? 1 : 0, 1);
    asm volatile("cp.async.wait_group 1;");
    __syncthreads();

    for (int t = 0; t < T_; ++t) {
        const int buf = t % 3;
        {
            int tn = (t + 2 < T_) ? t + 2 : T_ - 1;
            do_prefetch(tn, (t + 2) % 3);
        }

        // ---- Phase A: gate h-GEMM partials -> psg
#pragma unroll
        for (int mh = 0; mh < 2; mh++) {
            const int mbase = mh * 4;
            const int mcnt  = mh ? 3 : 4;
            ull acc[4][2];
#pragma unroll
            for (int mm = 0; mm < 4; mm++)
                { acc[mm][0] = 0ull; acc[mm][1] = 0ull; }
#pragma unroll
            for (int mm = 0; mm < 4; mm++) {
                if (mm >= mcnt) break;
                const ulonglong2* p =
                    (const ulonglong2*)&S->sh[mbase + mm][gks * 16];
                ulonglong2 v0 = p[0], v1 = p[1], v2 = p[2], v3 = p[3];
#pragma unroll
                for (int c = 0; c < 2; c++) {
                    acc[mm][c] = ffma2(wg2[0][c], v0.x, acc[mm][c]);
                    acc[mm][c] = ffma2(wg2[1][c], v0.y, acc[mm][c]);
                    acc[mm][c] = ffma2(wg2[2][c], v1.x, acc[mm][c]);
                    acc[mm][c] = ffma2(wg2[3][c], v1.y, acc[mm][c]);
                    acc[mm][c] = ffma2(wg2[4][c], v2.x, acc[mm][c]);
                    acc[mm][c] = ffma2(wg2[5][c], v2.y, acc[mm][c]);
                    acc[mm][c] = ffma2(wg2[6][c], v3.x, acc[mm][c]);
                    acc[mm][c] = ffma2(wg2[7][c], v3.y, acc[mm][c]);
                }
            }
#pragma unroll
            for (int mm = 0; mm < 4; mm++) {
                if (mm >= mcnt) break;
                *(float2*)&S->psg[(gks * M_ + mbase + mm) * 128 + 2 * gng] =
                    make_float2(hadd2(acc[mm][0]), hadd2(acc[mm][1]));
            }
        }
        __syncthreads();

        // ---- Phase B: r-gate finalize (tree adds) -> srh
        if (tid < M_ * 32) {
            int m = tid >> 5, n0 = (tid & 31) * 2;
            ull p0 = *(const ull*)&S->psg[(0 * M_ + m) * 128 + n0];
            ull p1 = *(const ull*)&S->psg[(1 * M_ + m) * 128 + n0];
            ull p2 = *(const ull*)&S->psg[(2 * M_ + m) * 128 + n0];
            ull p3 = *(const ull*)&S->psg[(3 * M_ + m) * 128 + n0];
            ull s  = add2(add2(p0, p1), add2(p2, p3));
            s = add2(s, *(const ull*)&S->sy1[buf][m][n0]);
            float g0, g1; unpack2(s, g0, g1);
            g0 = sigmoid_f(g0); g1 = sigmoid_f(g1);
            float2 hv = *(const float2*)&S->sh[m][n0];
            *(float2*)&S->srh[m][n0] = make_float2(g0 * hv.x, g1 * hv.y);
        }
        __syncthreads();

        // ---- Phase C: cand rh-GEMM partials -> psc
#pragma unroll
        for (int mh = 0; mh < 2; mh++) {
            const int mbase = mh * 4;
            const int mcnt  = mh ? 3 : 4;
            ull acc[4][2];
#pragma unroll
            for (int mm = 0; mm < 4; mm++)
                { acc[mm][0] = 0ull; acc[mm][1] = 0ull; }
#pragma unroll
            for (int mm = 0; mm < 4; mm++) {
                if (mm >= mcnt) break;
                const ulonglong2* p =
                    (const ulonglong2*)&S->srh[mbase + mm][cks * 8];
                ulonglong2 v0 = p[0], v1 = p[1];
#pragma unroll
                for (int c = 0; c < 2; c++) {
                    acc[mm][c] = ffma2(wc2[0][c], v0.x, acc[mm][c]);
                    acc[mm][c] = ffma2(wc2[1][c], v0.y, acc[mm][c]);
                    acc[mm][c] = ffma2(wc2[2][c], v1.x, acc[mm][c]);
                    acc[mm][c] = ffma2(wc2[3][c], v1.y, acc[mm][c]);
                }
            }
#pragma unroll
            for (int mm = 0; mm < 4; mm++) {
                if (mm >= mcnt) break;
                *(float2*)&S->psc[(cks * M_ + mbase + mm) * 64 + 2 * cng] =
                    make_float2(hadd2(acc[mm][0]), hadd2(acc[mm][1]));
            }
        }
        __syncthreads();

        // ---- Phase D: u-gate + cand finalize (tree adds) + update + output
        if (tid < M_ * 32) {
            int m = tid >> 5, n0 = (tid & 31) * 2;
            ull q0 = *(const ull*)&S->psg[(0 * M_ + m) * 128 + 64 + n0];
            ull q1 = *(const ull*)&S->psg[(1 * M_ + m) * 128 + 64 + n0];
            ull q2 = *(const ull*)&S->psg[(2 * M_ + m) * 128 + 64 + n0];
            ull q3 = *(const ull*)&S->psg[(3 * M_ + m) * 128 + 64 + n0];
            ull su_ = add2(add2(q0, q1), add2(q2, q3));
            su_ = add2(su_, *(const ull*)&S->sy1[buf][m][64 + n0]);
            float u0, u1; unpack2(su_, u0, u1);
            u0 = sigmoid_f(u0); u1 = sigmoid_f(u1);
            ull c0_ = *(const ull*)&S->psc[(0 * M_ + m) * 64 + n0];
            ull c1_ = *(const ull*)&S->psc[(1 * M_ + m) * 64 + n0];
            ull c2_ = *(const ull*)&S->psc[(2 * M_ + m) * 64 + n0];
            ull c3_ = *(const ull*)&S->psc[(3 * M_ + m) * 64 + n0];
            ull c4_ = *(const ull*)&S->psc[(4 * M_ + m) * 64 + n0];
            ull c5_ = *(const ull*)&S->psc[(5 * M_ + m) * 64 + n0];
            ull c6_ = *(const ull*)&S->psc[(6 * M_ + m) * 64 + n0];
            ull c7_ = *(const ull*)&S->psc[(7 * M_ + m) * 64 + n0];
            ull sc_ = add2(add2(add2(c0_, c1_), add2(c2_, c3_)),
                           add2(add2(c4_, c5_), add2(c6_, c7_)));
            sc_ = add2(sc_, *(const ull*)&S->sy2[buf][m][n0]);
            float c0, c1; unpack2(sc_, c0, c1);
            c0 = tanh_f(c0); c1 = tanh_f(c1);
            float2 hv = *(const float2*)&S->sh[m][n0];
            float a   = S->sa[buf][m];
            float uh0 = (1.0f - a) * u0;
            float uh1 = (1.0f - a) * u1;
            float hn0 = uh0 * hv.x + (1.0f - uh0) * c0;
            float hn1 = uh1 * hv.y + (1.0f - uh1) * c1;
            bool valid = (t < S->sl[m]);
            *(float2*)&S->sh[m][n0] =
                make_float2(valid ? hn0 : hv.x, valid ? hn1 : hv.y);
            int b = b0 + m;
            if (b < B_)
                *(float2*)&out[((size_t)b * T_ + t) * 64 + n0] =
                    make_float2(valid ? hn0 : 0.0f, valid ? hn1 : 0.0f);
        }
        asm volatile("cp.async.wait_group 1;");
        __syncthreads();
    }
    asm volatile("cp.async.wait_group 0;");
}

extern "C" void kernel_launch(void* const* d_in, const int* in_sizes, int n_in,
                              void* d_out, int out_size) {
    const float* x   = (const float*)d_in[0];
    const int*   sl  = (const int*)  d_in[1];
    const float* att = (const float*)d_in[2];
    const float* gk  = (const float*)d_in[3];
    const float* gb  = (const float*)d_in[4];
    const float* ck  = (const float*)d_in[5];
    const float* cb  = (const float*)d_in[6];
    float* out = (float*)d_out;

    pre_kernel<<<PGRID, PT>>>(x, gk, gb, ck, cb);

    cudaFuncSetAttribute(augru_rec,
                         cudaFuncAttributeMaxDynamicSharedMemorySize, RSMEM_BYTES);
    augru_rec<<<NCTA_R, RTHREADS, RSMEM_BYTES>>>(sl, att, gk, ck, out);
}

// round 15
// speedup vs baseline: 3.2246x; 1.2147x over previous
#include <cuda_runtime.h>
#include <cuda_bf16.h>
#include <cstdint>

// AUGRU, B=2048, T=200, D=H=64. Both kernels on the tensor pipe (mma.sync).
//  K1 (pre): R14 verbatim (measured ~99us): Y = x@[Wgx|Wcx]+bias,
//            m16n8k16 bf16, 3-term split-bf16.
//  K2 (rec): NEW — recurrence GEMMs as padded m16 MMA tiles. No partial
//            buffers/reductions; gate output feeds cand A-tile directly;
//            cand update writes next step's h A-tile. 2 syncs/step.

#define B_ 2048
#define T_ 200
#define D_ 64
#define H_ 64
#define BT_ (B_ * T_)

__device__ float Y1g[BT_ * 128];
__device__ float Y2g[BT_ * 64];

__device__ __forceinline__ float sigmoid_f(float x) {
    return __fdividef(1.0f, 1.0f + __expf(-x));
}
__device__ __forceinline__ float tanh_f(float x) {
    float e = __expf(2.0f * x);
    return 1.0f - __fdividef(2.0f, e + 1.0f);
}
__device__ __forceinline__ void cpa16(void* s, const void* g) {
    uint32_t sa = (uint32_t)__cvta_generic_to_shared(s);
    asm volatile("cp.async.ca.shared.global [%0], [%1], 16;" :: "r"(sa), "l"(g));
}
__device__ __forceinline__ void cpa4(void* s, const void* g) {
    uint32_t sa = (uint32_t)__cvta_generic_to_shared(s);
    asm volatile("cp.async.ca.shared.global [%0], [%1], 4;" :: "r"(sa), "l"(g));
}
__device__ __forceinline__ uint32_t smem_u32(const void* p) {
    uint32_t a;
    asm("{ .reg .u64 t; cvta.to.shared.u64 t, %1; cvt.u32.u64 %0, t; }"
        : "=r"(a) : "l"(p));
    return a;
}
__device__ __forceinline__ uint32_t bfpack(float a, float b) {
    __nv_bfloat162 t = __floats2bfloat162_rn(a, b);
    uint32_t r; memcpy(&r, &t, 4); return r;
}
__device__ __forceinline__ void bfsplit(float v, float& hi, float& lo) {
    __nv_bfloat16 h = __float2bfloat16(v);
    hi = __bfloat162float(h);
    lo = v - hi;
}
__device__ __forceinline__ void mma16816(float& c0, float& c1, float& c2, float& c3,
                                         uint32_t a0, uint32_t a1, uint32_t a2, uint32_t a3,
                                         uint32_t b0, uint32_t b1) {
    asm volatile(
        "mma.sync.aligned.m16n8k16.row.col.f32.bf16.bf16.f32 "
        "{%0,%1,%2,%3}, {%4,%5,%6,%7}, {%8,%9}, {%0,%1,%2,%3};"
        : "+f"(c0), "+f"(c1), "+f"(c2), "+f"(c3)
        : "r"(a0), "r"(a1), "r"(a2), "r"(a3), "r"(b0), "r"(b1));
}
__device__ __forceinline__ void ldmx4(uint32_t& r0, uint32_t& r1,
                                      uint32_t& r2, uint32_t& r3, uint32_t addr) {
    asm volatile("ldmatrix.sync.aligned.m8n8.x4.shared.b16 {%0,%1,%2,%3}, [%4];"
                 : "=r"(r0), "=r"(r1), "=r"(r2), "=r"(r3) : "r"(addr));
}
// swizzled byte offset in a 16x64-bf16 tile (128B rows)
__device__ __forceinline__ uint32_t toff(int row, int col) {
    return (uint32_t)row * 128 +
           ((((uint32_t)(col >> 3) ^ (uint32_t)(row & 7)) & 7) << 4) +
           (uint32_t)(col & 7) * 2;
}

// ============================ K1: precompute (R14, ~99us) ===================
#define PT 256
#define PGRID 296
#define NTILE (BT_ / 16)

__global__ __launch_bounds__(PT, 2)
void pre_kernel(const float* __restrict__ x,
                const float* __restrict__ gk,
                const float* __restrict__ gb,
                const float* __restrict__ ck,
                const float* __restrict__ cb)
{
    __shared__ __align__(128) char sA[4096];
    const uint32_t sAhi = smem_u32(sA);
    const uint32_t sAlo = sAhi + 2048;

    const int tid  = threadIdx.x;
    const int wid  = tid >> 5;
    const int lane = tid & 31;
    const int lq   = lane & 3;
    const int ln   = lane >> 2;

    uint32_t Bh[3][4][2], Bl[3][4][2];
    float2 bias[3];
#pragma unroll
    for (int b = 0; b < 3; b++) {
        const int n = wid * 24 + b * 8 + ln;
        const int cb0 = wid * 24 + b * 8 + 2 * lq;
        if (cb0 < 128) bias[b] = make_float2(gb[cb0], gb[cb0 + 1]);
        else           bias[b] = make_float2(cb[cb0 - 128], cb[cb0 - 127]);
#pragma unroll
        for (int ks = 0; ks < 4; ks++) {
            const int k0 = ks * 16 + 2 * lq;
            float hi[4], lo[4];
#pragma unroll
            for (int j = 0; j < 4; j++) {
                const int k = k0 + (j >> 1) * 8 + (j & 1);
                float w = (n < 128) ? gk[k * 128 + n] : ck[k * 64 + (n - 128)];
                bfsplit(w, hi[j], lo[j]);
            }
            Bh[b][ks][0] = bfpack(hi[0], hi[1]);
            Bh[b][ks][1] = bfpack(hi[2], hi[3]);
            Bl[b][ks][0] = bfpack(lo[0], lo[1]);
            Bl[b][ks][1] = bfpack(lo[2], lo[3]);
        }
    }

    const int r  = tid >> 4;
    const int kq = (tid & 15) * 4;
    const uint32_t aoff = toff(r, kq);

    float4 pf = make_float4(0.f, 0.f, 0.f, 0.f);
    if (blockIdx.x < NTILE)
        pf = *(const float4*)(x + ((size_t)blockIdx.x * 16 + r) * 64 + kq);

    for (int tile = blockIdx.x; tile < NTILE; tile += PGRID) {
        {
            float hx, lx, hy, ly, hz, lz, hw, lw;
            bfsplit(pf.x, hx, lx); bfsplit(pf.y, hy, ly);
            bfsplit(pf.z, hz, lz); bfsplit(pf.w, hw, lw);
            *(uint32_t*)(sA + aoff)            = bfpack(hx, hy);
            *(uint32_t*)(sA + aoff + 4)        = bfpack(hz, hw);
            *(uint32_t*)(sA + 2048 + aoff)     = bfpack(lx, ly);
            *(uint32_t*)(sA + 2048 + aoff + 4) = bfpack(lz, lw);
        }
        __syncthreads();
        {
            int nt = tile + PGRID;
            if (nt < NTILE)
                pf = *(const float4*)(x + ((size_t)nt * 16 + r) * 64 + kq);
        }

        float c[3][4];
#pragma unroll
        for (int b = 0; b < 3; b++) {
            c[b][0] = bias[b].x; c[b][1] = bias[b].y;
            c[b][2] = bias[b].x; c[b][3] = bias[b].y;
        }

        const int tI = lane >> 3;
        const int rr = ((tI & 1) << 3) + (lane & 7);
        const int cI = tI >> 1;

#pragma unroll
        for (int ks = 0; ks < 4; ks++) {
            const uint32_t ch = (uint32_t)(2 * ks + cI);
            const uint32_t la = (uint32_t)rr * 128 +
                                (((ch ^ (uint32_t)(rr & 7)) & 7) << 4);
            uint32_t ah0, ah1, ah2, ah3, al0, al1, al2, al3;
            ldmx4(ah0, ah1, ah2, ah3, sAhi + la);
            ldmx4(al0, al1, al2, al3, sAlo + la);
#pragma unroll
            for (int b = 0; b < 3; b++) {
                mma16816(c[b][0], c[b][1], c[b][2], c[b][3],
                         ah0, ah1, ah2, ah3, Bh[b][ks][0], Bh[b][ks][1]);
                mma16816(c[b][0], c[b][1], c[b][2], c[b][3],
                         ah0, ah1, ah2, ah3, Bl[b][ks][0], Bl[b][ks][1]);
                mma16816(c[b][0], c[b][1], c[b][2], c[b][3],
                         al0, al1, al2, al3, Bh[b][ks][0], Bh[b][ks][1]);
            }
        }

        {
            const size_t row0 = (size_t)tile * 16 + ln;
#pragma unroll
            for (int b = 0; b < 3; b++) {
                const int col = wid * 24 + b * 8 + 2 * lq;
                if (col < 128) {
                    *(float2*)&Y1g[row0 * 128 + col]       = make_float2(c[b][0], c[b][1]);
                    *(float2*)&Y1g[(row0 + 8) * 128 + col] = make_float2(c[b][2], c[b][3]);
                } else {
                    *(float2*)&Y2g[row0 * 64 + col - 128]       = make_float2(c[b][0], c[b][1]);
                    *(float2*)&Y2g[(row0 + 8) * 64 + col - 128] = make_float2(c[b][2], c[b][3]);
                }
            }
        }
        __syncthreads();
    }
}

// ============================ K2: recurrence (tensor) =======================
#define M_ 7
#define RTHREADS 256
#define NCTA_R ((B_ + M_ - 1) / M_)   // 293

__global__ __launch_bounds__(RTHREADS, 2)
void augru_rec(const int*   __restrict__ slen_g,
               const float* __restrict__ att,   // [B,T]
               const float* __restrict__ gk,
               const float* __restrict__ ck,
               float*       __restrict__ out)
{
    __shared__ float sy1[3][M_][128];
    __shared__ float sy2[3][M_][64];
    __shared__ float sh[M_][64];
    __shared__ float su[M_][64];
    __shared__ __align__(128) char hA[2][2048];   // h  hi/lo bf16 tiles 16x64
    __shared__ __align__(128) char rA[2][2048];   // rh hi/lo bf16 tiles 16x64
    __shared__ float sa[3][8];
    __shared__ int   sl[8];

    const int tid  = threadIdx.x;
    const int wid  = tid >> 5;
    const int lane = tid & 31;
    const int lq   = lane & 3;
    const int ln   = lane >> 2;
    const int b0   = blockIdx.x * M_;

    // ---- register-resident W fragments (3-term split) ----
    // gate: warp w owns n-blocks {2w, 2w+1} => cols 16w+8bb+...
    uint32_t GBh[2][4][2], GBl[2][4][2];
#pragma unroll
    for (int bb = 0; bb < 2; bb++) {
        const int n = 16 * wid + 8 * bb + ln;
#pragma unroll
        for (int ks = 0; ks < 4; ks++) {
            const int k0 = ks * 16 + 2 * lq;
            float hi[4], lo[4];
#pragma unroll
            for (int j = 0; j < 4; j++) {
                const int k = k0 + (j >> 1) * 8 + (j & 1);
                bfsplit(gk[(64 + k) * 128 + n], hi[j], lo[j]);
            }
            GBh[bb][ks][0] = bfpack(hi[0], hi[1]);
            GBh[bb][ks][1] = bfpack(hi[2], hi[3]);
            GBl[bb][ks][0] = bfpack(lo[0], lo[1]);
            GBl[bb][ks][1] = bfpack(lo[2], lo[3]);
        }
    }
    // cand: warp w owns n-block w => cols 8w+...
    uint32_t CBh[4][2], CBl[4][2];
    {
        const int n = 8 * wid + ln;
#pragma unroll
        for (int ks = 0; ks < 4; ks++) {
            const int k0 = ks * 16 + 2 * lq;
            float hi[4], lo[4];
#pragma unroll
            for (int j = 0; j < 4; j++) {
                const int k = k0 + (j >> 1) * 8 + (j & 1);
                bfsplit(ck[(64 + k) * 64 + n], hi[j], lo[j]);
            }
            CBh[ks][0] = bfpack(hi[0], hi[1]);
            CBh[ks][1] = bfpack(hi[2], hi[3]);
            CBl[ks][0] = bfpack(lo[0], lo[1]);
            CBl[ks][1] = bfpack(lo[2], lo[3]);
        }
    }

    // ---- init: h=0, tiles zeroed (incl. pad rows 7-15), lens ----
    for (int i = tid; i < M_ * 64; i += RTHREADS) (&sh[0][0])[i] = 0.0f;
    for (int i = tid; i < 1024; i += RTHREADS) {
        ((uint32_t*)hA)[i] = 0u;
        ((uint32_t*)rA)[i] = 0u;
    }
    if (tid < M_) {
        int b = b0 + tid; if (b >= B_) b = B_ - 1;
        sl[tid] = slen_g[b];
    }

    // ---- Y/att prefetch (R12 scheme) ----
    const int y1m = tid >> 5, y1q = tid & 31;
    const int y2m = tid >> 4, y2q = tid & 15;
    int by1 = b0 + y1m; if (by1 >= B_) by1 = B_ - 1;
    int by2 = b0 + y2m; if (by2 >= B_) by2 = B_ - 1;
    int ba  = b0 + tid; if (ba  >= B_) ba  = B_ - 1;

    auto do_prefetch = [&](int tt, int bb) {
        if (tid < 224)
            cpa16((char*)&sy1[bb][0][0] + tid * 16,
                  &Y1g[((size_t)by1 * T_ + tt) * 128 + y1q * 4]);
        if (tid < 112)
            cpa16((char*)&sy2[bb][0][0] + tid * 16,
                  &Y2g[((size_t)by2 * T_ + tt) * 64 + y2q * 4]);
        if (tid < M_)
            cpa4(&sa[bb][tid], &att[(size_t)ba * T_ + tt]);
        asm volatile("cp.async.commit_group;");
    };

    do_prefetch(0, 0);
    do_prefetch(1 < T_ ? 1 : 0, 1);
    asm volatile("cp.async.wait_group 1;");
    __syncthreads();

    // ldmatrix lane addressing (R14-verified tile order)
    const int tI = lane >> 3;
    const int rr = ((tI & 1) << 3) + (lane & 7);
    const int cI = tI >> 1;
    const uint32_t hA0 = smem_u32(hA[0]), hA1 = smem_u32(hA[1]);
    const uint32_t rA0 = smem_u32(rA[0]), rA1 = smem_u32(rA[1]);

    const int r0 = (ln < M_) ? ln : 0;   // clamped acc-init row

    for (int t = 0; t < T_; ++t) {
        const int buf = t % 3;
        {
            int tn = (t + 2 < T_) ? t + 2 : T_ - 1;
            do_prefetch(tn, (t + 2) % 3);
        }

        // ================= gate phase: G = Y1 + h@Wgh =================
        float c[2][4];
#pragma unroll
        for (int bb = 0; bb < 2; bb++) {
            const int col0 = 16 * wid + 8 * bb + 2 * lq;
            c[bb][0] = sy1[buf][r0][col0];
            c[bb][1] = sy1[buf][r0][col0 + 1];
            c[bb][2] = 0.0f; c[bb][3] = 0.0f;
        }
#pragma unroll
        for (int ks = 0; ks < 4; ks++) {
            const uint32_t ch = (uint32_t)(2 * ks + cI);
            const uint32_t la = (uint32_t)rr * 128 +
                                (((ch ^ (uint32_t)(rr & 7)) & 7) << 4);
            uint32_t ah0, ah1, ah2, ah3, al0, al1, al2, al3;
            ldmx4(ah0, ah1, ah2, ah3, hA0 + la);
            ldmx4(al0, al1, al2, al3, hA1 + la);
#pragma unroll
            for (int bb = 0; bb < 2; bb++) {
                mma16816(c[bb][0], c[bb][1], c[bb][2], c[bb][3],
                         ah0, ah1, ah2, ah3, GBh[bb][ks][0], GBh[bb][ks][1]);
                mma16816(c[bb][0], c[bb][1], c[bb][2], c[bb][3],
                         ah0, ah1, ah2, ah3, GBl[bb][ks][0], GBl[bb][ks][1]);
                mma16816(c[bb][0], c[bb][1], c[bb][2], c[bb][3],
                         al0, al1, al2, al3, GBh[bb][ks][0], GBh[bb][ks][1]);
            }
        }
        if (ln < M_) {
#pragma unroll
            for (int bb = 0; bb < 2; bb++) {
                const int j = 16 * wid + 8 * bb + 2 * lq;
                float g0 = sigmoid_f(c[bb][0]);
                float g1 = sigmoid_f(c[bb][1]);
                if (wid < 4) {
                    // r-gate -> rh bf16 tiles (cand A operand)
                    float rh0 = g0 * sh[ln][j];
                    float rh1 = g1 * sh[ln][j + 1];
                    float h0, l0, h1, l1;
                    bfsplit(rh0, h0, l0); bfsplit(rh1, h1, l1);
                    uint32_t o = toff(ln, j);
                    *(uint32_t*)(rA[0] + o) = bfpack(h0, h1);
                    *(uint32_t*)(rA[1] + o) = bfpack(l0, l1);
                } else {
                    // u-gate -> su
                    *(float2*)&su[ln][j - 64] = make_float2(g0, g1);
                }
            }
        }
        __syncthreads();

        // ================= cand phase: C = Y2 + rh@Wch, update h ========
        float d0, d1, d2, d3;
        {
            const int col0 = 8 * wid + 2 * lq;
            d0 = sy2[buf][r0][col0];
            d1 = sy2[buf][r0][col0 + 1];
            d2 = 0.0f; d3 = 0.0f;
        }
#pragma unroll
        for (int ks = 0; ks < 4; ks++) {
            const uint32_t ch = (uint32_t)(2 * ks + cI);
            const uint32_t la = (uint32_t)rr * 128 +
                                (((ch ^ (uint32_t)(rr & 7)) & 7) << 4);
            uint32_t ah0, ah1, ah2, ah3, al0, al1, al2, al3;
            ldmx4(ah0, ah1, ah2, ah3, rA0 + la);
            ldmx4(al0, al1, al2, al3, rA1 + la);
            mma16816(d0, d1, d2, d3, ah0, ah1, ah2, ah3, CBh[ks][0], CBh[ks][1]);
            mma16816(d0, d1, d2, d3, ah0, ah1, ah2, ah3, CBl[ks][0], CBl[ks][1]);
            mma16816(d0, d1, d2, d3, al0, al1, al2, al3, CBh[ks][0], CBh[ks][1]);
        }
        if (ln < M_) {
            const int m = ln;
            const int j = 8 * wid + 2 * lq;
            float cc0 = tanh_f(d0);
            float cc1 = tanh_f(d1);
            float2 uv = *(const float2*)&su[m][j];
            float2 hv = *(const float2*)&sh[m][j];
            float a   = sa[buf][m];
            float uh0 = (1.0f - a) * uv.x;
            float uh1 = (1.0f - a) * uv.y;
            float hn0 = uh0 * hv.x + (1.0f - uh0) * cc0;
            float hn1 = uh1 * hv.y + (1.0f - uh1) * cc1;
            bool valid = (t < sl[m]);
            float hv0 = valid ? hn0 : hv.x;
            float hv1 = valid ? hn1 : hv.y;
            *(float2*)&sh[m][j] = make_float2(hv0, hv1);
            // next step's h A-tiles (hi/lo)
            float h0, l0, h1, l1;
            bfsplit(hv0, h0, l0); bfsplit(hv1, h1, l1);
            uint32_t o = toff(m, j);
            *(uint32_t*)(hA[0] + o) = bfpack(h0, h1);
            *(uint32_t*)(hA[1] + o) = bfpack(l0, l1);
            int b = b0 + m;
            if (b < B_)
                *(float2*)&out[((size_t)b * T_ + t) * 64 + j] =
                    make_float2(valid ? hn0 : 0.0f, valid ? hn1 : 0.0f);
        }
        asm volatile("cp.async.wait_group 1;");
        __syncthreads();
    }
    asm volatile("cp.async.wait_group 0;");
}

extern "C" void kernel_launch(void* const* d_in, const int* in_sizes, int n_in,
                              void* d_out, int out_size) {
    const float* x   = (const float*)d_in[0];
    const int*   sl  = (const int*)  d_in[1];
    const float* att = (const float*)d_in[2];
    const float* gk  = (const float*)d_in[3];
    const float* gb  = (const float*)d_in[4];
    const float* ck  = (const float*)d_in[5];
    const float* cb  = (const float*)d_in[6];
    float* out = (float*)d_out;

    pre_kernel<<<PGRID, PT>>>(x, gk, gb, ck, cb);
    augru_rec<<<NCTA_R, RTHREADS>>>(sl, att, gk, ck, out);
}

// round 16
// speedup vs baseline: 3.2630x; 1.0119x over previous
#include <cuda_runtime.h>
#include <cuda_bf16.h>
#include <cstdint>

// AUGRU, B=2048, T=200, D=H=64. Both kernels on the tensor pipe (mma.sync).
//  K1 (pre): R14 verbatim (~99us).
//  K2 (rec): R15 MMA recurrence with M=14 rows/CTA — uses BOTH fragment row
//            sets of the m16 tile (rows ln and ln+8). Grid 147, 1 CTA/SM.

#define B_ 2048
#define T_ 200
#define D_ 64
#define H_ 64
#define BT_ (B_ * T_)

__device__ float Y1g[BT_ * 128];
__device__ float Y2g[BT_ * 64];

__device__ __forceinline__ float sigmoid_f(float x) {
    return __fdividef(1.0f, 1.0f + __expf(-x));
}
__device__ __forceinline__ float tanh_f(float x) {
    float e = __expf(2.0f * x);
    return 1.0f - __fdividef(2.0f, e + 1.0f);
}
__device__ __forceinline__ void cpa16(void* s, const void* g) {
    uint32_t sa = (uint32_t)__cvta_generic_to_shared(s);
    asm volatile("cp.async.ca.shared.global [%0], [%1], 16;" :: "r"(sa), "l"(g));
}
__device__ __forceinline__ void cpa4(void* s, const void* g) {
    uint32_t sa = (uint32_t)__cvta_generic_to_shared(s);
    asm volatile("cp.async.ca.shared.global [%0], [%1], 4;" :: "r"(sa), "l"(g));
}
__device__ __forceinline__ uint32_t smem_u32(const void* p) {
    uint32_t a;
    asm("{ .reg .u64 t; cvta.to.shared.u64 t, %1; cvt.u32.u64 %0, t; }"
        : "=r"(a) : "l"(p));
    return a;
}
__device__ __forceinline__ uint32_t bfpack(float a, float b) {
    __nv_bfloat162 t = __floats2bfloat162_rn(a, b);
    uint32_t r; memcpy(&r, &t, 4); return r;
}
__device__ __forceinline__ void bfsplit(float v, float& hi, float& lo) {
    __nv_bfloat16 h = __float2bfloat16(v);
    hi = __bfloat162float(h);
    lo = v - hi;
}
__device__ __forceinline__ void mma16816(float& c0, float& c1, float& c2, float& c3,
                                         uint32_t a0, uint32_t a1, uint32_t a2, uint32_t a3,
                                         uint32_t b0, uint32_t b1) {
    asm volatile(
        "mma.sync.aligned.m16n8k16.row.col.f32.bf16.bf16.f32 "
        "{%0,%1,%2,%3}, {%4,%5,%6,%7}, {%8,%9}, {%0,%1,%2,%3};"
        : "+f"(c0), "+f"(c1), "+f"(c2), "+f"(c3)
        : "r"(a0), "r"(a1), "r"(a2), "r"(a3), "r"(b0), "r"(b1));
}
__device__ __forceinline__ void ldmx4(uint32_t& r0, uint32_t& r1,
                                      uint32_t& r2, uint32_t& r3, uint32_t addr) {
    asm volatile("ldmatrix.sync.aligned.m8n8.x4.shared.b16 {%0,%1,%2,%3}, [%4];"
                 : "=r"(r0), "=r"(r1), "=r"(r2), "=r"(r3) : "r"(addr));
}
__device__ __forceinline__ uint32_t toff(int row, int col) {
    return (uint32_t)row * 128 +
           ((((uint32_t)(col >> 3) ^ (uint32_t)(row & 7)) & 7) << 4) +
           (uint32_t)(col & 7) * 2;
}

// ============================ K1: precompute (R14, ~99us) ===================
#define PT 256
#define PGRID 296
#define NTILE (BT_ / 16)

__global__ __launch_bounds__(PT, 2)
void pre_kernel(const float* __restrict__ x,
                const float* __restrict__ gk,
                const float* __restrict__ gb,
                const float* __restrict__ ck,
                const float* __restrict__ cb)
{
    __shared__ __align__(128) char sA[4096];
    const uint32_t sAhi = smem_u32(sA);
    const uint32_t sAlo = sAhi + 2048;

    const int tid  = threadIdx.x;
    const int wid  = tid >> 5;
    const int lane = tid & 31;
    const int lq   = lane & 3;
    const int ln   = lane >> 2;

    uint32_t Bh[3][4][2], Bl[3][4][2];
    float2 bias[3];
#pragma unroll
    for (int b = 0; b < 3; b++) {
        const int n = wid * 24 + b * 8 + ln;
        const int cb0 = wid * 24 + b * 8 + 2 * lq;
        if (cb0 < 128) bias[b] = make_float2(gb[cb0], gb[cb0 + 1]);
        else           bias[b] = make_float2(cb[cb0 - 128], cb[cb0 - 127]);
#pragma unroll
        for (int ks = 0; ks < 4; ks++) {
            const int k0 = ks * 16 + 2 * lq;
            float hi[4], lo[4];
#pragma unroll
            for (int j = 0; j < 4; j++) {
                const int k = k0 + (j >> 1) * 8 + (j & 1);
                float w = (n < 128) ? gk[k * 128 + n] : ck[k * 64 + (n - 128)];
                bfsplit(w, hi[j], lo[j]);
            }
            Bh[b][ks][0] = bfpack(hi[0], hi[1]);
            Bh[b][ks][1] = bfpack(hi[2], hi[3]);
            Bl[b][ks][0] = bfpack(lo[0], lo[1]);
            Bl[b][ks][1] = bfpack(lo[2], lo[3]);
        }
    }

    const int r  = tid >> 4;
    const int kq = (tid & 15) * 4;
    const uint32_t aoff = toff(r, kq);

    float4 pf = make_float4(0.f, 0.f, 0.f, 0.f);
    if (blockIdx.x < NTILE)
        pf = *(const float4*)(x + ((size_t)blockIdx.x * 16 + r) * 64 + kq);

    for (int tile = blockIdx.x; tile < NTILE; tile += PGRID) {
        {
            float hx, lx, hy, ly, hz, lz, hw, lw;
            bfsplit(pf.x, hx, lx); bfsplit(pf.y, hy, ly);
            bfsplit(pf.z, hz, lz); bfsplit(pf.w, hw, lw);
            *(uint32_t*)(sA + aoff)            = bfpack(hx, hy);
            *(uint32_t*)(sA + aoff + 4)        = bfpack(hz, hw);
            *(uint32_t*)(sA + 2048 + aoff)     = bfpack(lx, ly);
            *(uint32_t*)(sA + 2048 + aoff + 4) = bfpack(lz, lw);
        }
        __syncthreads();
        {
            int nt = tile + PGRID;
            if (nt < NTILE)
                pf = *(const float4*)(x + ((size_t)nt * 16 + r) * 64 + kq);
        }

        float c[3][4];
#pragma unroll
        for (int b = 0; b < 3; b++) {
            c[b][0] = bias[b].x; c[b][1] = bias[b].y;
            c[b][2] = bias[b].x; c[b][3] = bias[b].y;
        }

        const int tI = lane >> 3;
        const int rr = ((tI & 1) << 3) + (lane & 7);
        const int cI = tI >> 1;

#pragma unroll
        for (int ks = 0; ks < 4; ks++) {
            const uint32_t ch = (uint32_t)(2 * ks + cI);
            const uint32_t la = (uint32_t)rr * 128 +
                                (((ch ^ (uint32_t)(rr & 7)) & 7) << 4);
            uint32_t ah0, ah1, ah2, ah3, al0, al1, al2, al3;
            ldmx4(ah0, ah1, ah2, ah3, sAhi + la);
            ldmx4(al0, al1, al2, al3, sAlo + la);
#pragma unroll
            for (int b = 0; b < 3; b++) {
                mma16816(c[b][0], c[b][1], c[b][2], c[b][3],
                         ah0, ah1, ah2, ah3, Bh[b][ks][0], Bh[b][ks][1]);
                mma16816(c[b][0], c[b][1], c[b][2], c[b][3],
                         ah0, ah1, ah2, ah3, Bl[b][ks][0], Bl[b][ks][1]);
                mma16816(c[b][0], c[b][1], c[b][2], c[b][3],
                         al0, al1, al2, al3, Bh[b][ks][0], Bh[b][ks][1]);
            }
        }

        {
            const size_t row0 = (size_t)tile * 16 + ln;
#pragma unroll
            for (int b = 0; b < 3; b++) {
                const int col = wid * 24 + b * 8 + 2 * lq;
                if (col < 128) {
                    *(float2*)&Y1g[row0 * 128 + col]       = make_float2(c[b][0], c[b][1]);
                    *(float2*)&Y1g[(row0 + 8) * 128 + col] = make_float2(c[b][2], c[b][3]);
                } else {
                    *(float2*)&Y2g[row0 * 64 + col - 128]       = make_float2(c[b][0], c[b][1]);
                    *(float2*)&Y2g[(row0 + 8) * 64 + col - 128] = make_float2(c[b][2], c[b][3]);
                }
            }
        }
        __syncthreads();
    }
}

// ============================ K2: recurrence (tensor, M=14) =================
#define M_ 14
#define RTHREADS 256
#define NCTA_R ((B_ + M_ - 1) / M_)   // 147

__global__ __launch_bounds__(RTHREADS, 2)
void augru_rec(const int*   __restrict__ slen_g,
               const float* __restrict__ att,   // [B,T]
               const float* __restrict__ gk,
               const float* __restrict__ ck,
               float*       __restrict__ out)
{
    __shared__ float sy1[3][M_][128];
    __shared__ float sy2[3][M_][64];
    __shared__ float sh[M_][64];
    __shared__ float su[M_][64];
    __shared__ __align__(128) char hA[2][2048];   // h  hi/lo bf16 tiles 16x64
    __shared__ __align__(128) char rA[2][2048];   // rh hi/lo bf16 tiles 16x64
    __shared__ float sa[3][16];
    __shared__ int   sl[16];

    const int tid  = threadIdx.x;
    const int wid  = tid >> 5;
    const int lane = tid & 31;
    const int lq   = lane & 3;
    const int ln   = lane >> 2;
    const int b0   = blockIdx.x * M_;

    // ---- register-resident W fragments (3-term split) ----
    uint32_t GBh[2][4][2], GBl[2][4][2];
#pragma unroll
    for (int bb = 0; bb < 2; bb++) {
        const int n = 16 * wid + 8 * bb + ln;
#pragma unroll
        for (int ks = 0; ks < 4; ks++) {
            const int k0 = ks * 16 + 2 * lq;
            float hi[4], lo[4];
#pragma unroll
            for (int j = 0; j < 4; j++) {
                const int k = k0 + (j >> 1) * 8 + (j & 1);
                bfsplit(gk[(64 + k) * 128 + n], hi[j], lo[j]);
            }
            GBh[bb][ks][0] = bfpack(hi[0], hi[1]);
            GBh[bb][ks][1] = bfpack(hi[2], hi[3]);
            GBl[bb][ks][0] = bfpack(lo[0], lo[1]);
            GBl[bb][ks][1] = bfpack(lo[2], lo[3]);
        }
    }
    uint32_t CBh[4][2], CBl[4][2];
    {
        const int n = 8 * wid + ln;
#pragma unroll
        for (int ks = 0; ks < 4; ks++) {
            const int k0 = ks * 16 + 2 * lq;
            float hi[4], lo[4];
#pragma unroll
            for (int j = 0; j < 4; j++) {
                const int k = k0 + (j >> 1) * 8 + (j & 1);
                bfsplit(ck[(64 + k) * 64 + n], hi[j], lo[j]);
            }
            CBh[ks][0] = bfpack(hi[0], hi[1]);
            CBh[ks][1] = bfpack(hi[2], hi[3]);
            CBl[ks][0] = bfpack(lo[0], lo[1]);
            CBl[ks][1] = bfpack(lo[2], lo[3]);
        }
    }

    // ---- init ----
    for (int i = tid; i < M_ * 64; i += RTHREADS) (&sh[0][0])[i] = 0.0f;
    for (int i = tid; i < 1024; i += RTHREADS) {
        ((uint32_t*)hA)[i] = 0u;
        ((uint32_t*)rA)[i] = 0u;
    }
    if (tid < M_) {
        int b = b0 + tid; if (b >= B_) b = B_ - 1;
        sl[tid] = slen_g[b];
    }

    // ---- Y/att prefetch (M=14: sy1 448 f4, sy2 224 f4) ----
    const int m1a = tid >> 5;                 // sy1 part 1 rows 0..7
    const int m1b = (tid + 256) >> 5;         // sy1 part 2 rows 8..13 (tid<192)
    const int m2  = tid >> 4;                 // sy2 rows 0..13 (tid<224)
    int b1a = b0 + m1a; if (b1a >= B_) b1a = B_ - 1;
    int b1b = b0 + ((m1b < M_) ? m1b : M_ - 1); if (b1b >= B_) b1b = B_ - 1;
    int b2  = b0 + ((m2 < M_) ? m2 : M_ - 1);   if (b2  >= B_) b2  = B_ - 1;
    int ba  = b0 + tid; if (ba >= B_) ba = B_ - 1;

    auto do_prefetch = [&](int tt, int bb) {
        {
            int q = tid & 31;
            cpa16((char*)&sy1[bb][0][0] + tid * 16,
                  &Y1g[((size_t)b1a * T_ + tt) * 128 + q * 4]);
        }
        if (tid < 192) {
            int idx = tid + 256, q = idx & 31;
            cpa16((char*)&sy1[bb][0][0] + idx * 16,
                  &Y1g[((size_t)b1b * T_ + tt) * 128 + q * 4]);
        }
        if (tid < 224) {
            int q = tid & 15;
            cpa16((char*)&sy2[bb][0][0] + tid * 16,
                  &Y2g[((size_t)b2 * T_ + tt) * 64 + q * 4]);
        }
        if (tid < M_)
            cpa4(&sa[bb][tid], &att[(size_t)ba * T_ + tt]);
        asm volatile("cp.async.commit_group;");
    };

    do_prefetch(0, 0);
    do_prefetch(1 < T_ ? 1 : 0, 1);
    asm volatile("cp.async.wait_group 1;");
    __syncthreads();

    const int tI = lane >> 3;
    const int rr = ((tI & 1) << 3) + (lane & 7);
    const int cI = tI >> 1;
    const uint32_t hA0 = smem_u32(hA[0]), hA1 = smem_u32(hA[1]);
    const uint32_t rA0 = smem_u32(rA[0]), rA1 = smem_u32(rA[1]);

    const int r0  = ln;                                // rows 0..7 (all < 14)
    const bool hi_valid = (ln < M_ - 8);               // ln < 6 -> row ln+8 real
    const int r1  = hi_valid ? (ln + 8) : 0;           // clamped init row

    for (int t = 0; t < T_; ++t) {
        const int buf = t % 3;
        {
            int tn = (t + 2 < T_) ? t + 2 : T_ - 1;
            do_prefetch(tn, (t + 2) % 3);
        }

        // ================= gate phase: G = Y1 + h@Wgh =================
        float c[2][4];
#pragma unroll
        for (int bb = 0; bb < 2; bb++) {
            const int col0 = 16 * wid + 8 * bb + 2 * lq;
            c[bb][0] = sy1[buf][r0][col0];
            c[bb][1] = sy1[buf][r0][col0 + 1];
            c[bb][2] = sy1[buf][r1][col0];
            c[bb][3] = sy1[buf][r1][col0 + 1];
        }
#pragma unroll
        for (int ks = 0; ks < 4; ks++) {
            const uint32_t ch = (uint32_t)(2 * ks + cI);
            const uint32_t la = (uint32_t)rr * 128 +
                                (((ch ^ (uint32_t)(rr & 7)) & 7) << 4);
            uint32_t ah0, ah1, ah2, ah3, al0, al1, al2, al3;
            ldmx4(ah0, ah1, ah2, ah3, hA0 + la);
            ldmx4(al0, al1, al2, al3, hA1 + la);
#pragma unroll
            for (int bb = 0; bb < 2; bb++) {
                mma16816(c[bb][0], c[bb][1], c[bb][2], c[bb][3],
                         ah0, ah1, ah2, ah3, GBh[bb][ks][0], GBh[bb][ks][1]);
                mma16816(c[bb][0], c[bb][1], c[bb][2], c[bb][3],
                         ah0, ah1, ah2, ah3, GBl[bb][ks][0], GBl[bb][ks][1]);
                mma16816(c[bb][0], c[bb][1], c[bb][2], c[bb][3],
                         al0, al1, al2, al3, GBh[bb][ks][0], GBh[bb][ks][1]);
            }
        }
#pragma unroll
        for (int bb = 0; bb < 2; bb++) {
            const int j = 16 * wid + 8 * bb + 2 * lq;
            float g0 = sigmoid_f(c[bb][0]);
            float g1 = sigmoid_f(c[bb][1]);
            float g2 = sigmoid_f(c[bb][2]);
            float g3 = sigmoid_f(c[bb][3]);
            if (wid < 4) {
                {
                    float rh0 = g0 * sh[r0][j];
                    float rh1 = g1 * sh[r0][j + 1];
                    float h0, l0, h1, l1;
                    bfsplit(rh0, h0, l0); bfsplit(rh1, h1, l1);
                    uint32_t o = toff(r0, j);
                    *(uint32_t*)(rA[0] + o) = bfpack(h0, h1);
                    *(uint32_t*)(rA[1] + o) = bfpack(l0, l1);
                }
                if (hi_valid) {
                    int m = ln + 8;
                    float rh0 = g2 * sh[m][j];
                    float rh1 = g3 * sh[m][j + 1];
                    float h0, l0, h1, l1;
                    bfsplit(rh0, h0, l0); bfsplit(rh1, h1, l1);
                    uint32_t o = toff(m, j);
                    *(uint32_t*)(rA[0] + o) = bfpack(h0, h1);
                    *(uint32_t*)(rA[1] + o) = bfpack(l0, l1);
                }
            } else {
                *(float2*)&su[r0][j - 64] = make_float2(g0, g1);
                if (hi_valid)
                    *(float2*)&su[ln + 8][j - 64] = make_float2(g2, g3);
            }
        }
        __syncthreads();

        // ================= cand phase: C = Y2 + rh@Wch, update h ========
        float d0, d1, d2, d3;
        {
            const int col0 = 8 * wid + 2 * lq;
            d0 = sy2[buf][r0][col0];
            d1 = sy2[buf][r0][col0 + 1];
            d2 = sy2[buf][r1][col0];
            d3 = sy2[buf][r1][col0 + 1];
        }
#pragma unroll
        for (int ks = 0; ks < 4; ks++) {
            const uint32_t ch = (uint32_t)(2 * ks + cI);
            const uint32_t la = (uint32_t)rr * 128 +
                                (((ch ^ (uint32_t)(rr & 7)) & 7) << 4);
            uint32_t ah0, ah1, ah2, ah3, al0, al1, al2, al3;
            ldmx4(ah0, ah1, ah2, ah3, rA0 + la);
            ldmx4(al0, al1, al2, al3, rA1 + la);
            mma16816(d0, d1, d2, d3, ah0, ah1, ah2, ah3, CBh[ks][0], CBh[ks][1]);
            mma16816(d0, d1, d2, d3, ah0, ah1, ah2, ah3, CBl[ks][0], CBl[ks][1]);
            mma16816(d0, d1, d2, d3, al0, al1, al2, al3, CBh[ks][0], CBh[ks][1]);
        }
        {
            const int j = 8 * wid + 2 * lq;
            // row r0
            {
                const int m = r0;
                float cc0 = tanh_f(d0);
                float cc1 = tanh_f(d1);
                float2 uv = *(const float2*)&su[m][j];
                float2 hv = *(const float2*)&sh[m][j];
                float a   = sa[buf][m];
                float uh0 = (1.0f - a) * uv.x;
                float uh1 = (1.0f - a) * uv.y;
                float hn0 = uh0 * hv.x + (1.0f - uh0) * cc0;
                float hn1 = uh1 * hv.y + (1.0f - uh1) * cc1;
                bool valid = (t < sl[m]);
                float hv0 = valid ? hn0 : hv.x;
                float hv1 = valid ? hn1 : hv.y;
                *(float2*)&sh[m][j] = make_float2(hv0, hv1);
                float h0, l0, h1, l1;
                bfsplit(hv0, h0, l0); bfsplit(hv1, h1, l1);
                uint32_t o = toff(m, j);
                *(uint32_t*)(hA[0] + o) = bfpack(h0, h1);
                *(uint32_t*)(hA[1] + o) = bfpack(l0, l1);
                int b = b0 + m;
                if (b < B_)
                    *(float2*)&out[((size_t)b * T_ + t) * 64 + j] =
                        make_float2(valid ? hn0 : 0.0f, valid ? hn1 : 0.0f);
            }
            // row ln+8
            if (hi_valid) {
                const int m = ln + 8;
                float cc0 = tanh_f(d2);
                float cc1 = tanh_f(d3);
                float2 uv = *(const float2*)&su[m][j];
                float2 hv = *(const float2*)&sh[m][j];
                float a   = sa[buf][m];
                float uh0 = (1.0f - a) * uv.x;
                float uh1 = (1.0f - a) * uv.y;
                float hn0 = uh0 * hv.x + (1.0f - uh0) * cc0;
                float hn1 = uh1 * hv.y + (1.0f - uh1) * cc1;
                bool valid = (t < sl[m]);
                float hv0 = valid ? hn0 : hv.x;
                float hv1 = valid ? hn1 : hv.y;
                *(float2*)&sh[m][j] = make_float2(hv0, hv1);
                float h0, l0, h1, l1;
                bfsplit(hv0, h0, l0); bfsplit(hv1, h1, l1);
                uint32_t o = toff(m, j);
                *(uint32_t*)(hA[0] + o) = bfpack(h0, h1);
                *(uint32_t*)(hA[1] + o) = bfpack(l0, l1);
                int b = b0 + m;
                if (b < B_)
                    *(float2*)&out[((size_t)b * T_ + t) * 64 + j] =
                        make_float2(valid ? hn0 : 0.0f, valid ? hn1 : 0.0f);
            }
        }
        asm volatile("cp.async.wait_group 1;");
        __syncthreads();
    }
    asm volatile("cp.async.wait_group 0;");
}

extern "C" void kernel_launch(void* const* d_in, const int* in_sizes, int n_in,
                              void* d_out, int out_size) {
    const float* x   = (const float*)d_in[0];
    const int*   sl  = (const int*)  d_in[1];
    const float* att = (const float*)d_in[2];
    const float* gk  = (const float*)d_in[3];
    const float* gb  = (const float*)d_in[4];
    const float* ck  = (const float*)d_in[5];
    const float* cb  = (const float*)d_in[6];
    float* out = (float*)d_out;

    pre_kernel<<<PGRID, PT>>>(x, gk, gb, ck, cb);
    augru_rec<<<NCTA_R, RTHREADS>>>(sl, att, gk, ck, out);
}